// round 2
// baseline (speedup 1.0000x reference)
#include <cuda_runtime.h>
#include <cuda_bf16.h>

#define HID 1024
#define NHEAD 16
#define HD 64
#define NB 2
#define SEQ 2048
#define MROWS (NB * SEQ)   // 4096

// Scratch (allocation-free rule: __device__ globals)
__device__ float g_q[MROWS * HID];
__device__ float g_k[MROWS * HID];
__device__ float g_v[MROWS * HID];
__device__ float g_att[MROWS * HID];

// ----------------------------------------------------------------------------
// SGEMM:  Y[M,N] = A[M,K] @ W[N,K]^T      (both K-contiguous row-major)
// 128x128 block tile, BK=8, 8x8 per-thread microtile, 256 threads.
// ----------------------------------------------------------------------------
__device__ __forceinline__ void gemm_nt_body(const float* __restrict__ A,
                                             const float* __restrict__ W,
                                             float* __restrict__ Y,
                                             int K, int N) {
    __shared__ float As[8][128];
    __shared__ float Bs[8][128];

    const int tid = threadIdx.x;
    const int bm  = blockIdx.y * 128;
    const int bn  = blockIdx.x * 128;
    const int lr  = tid >> 1;          // 0..127 : tile row for loads
    const int lc  = (tid & 1) << 2;    // 0 or 4 : k-offset for loads
    const int ty  = tid >> 4;          // 0..15
    const int tx  = tid & 15;          // 0..15

    float acc[8][8];
#pragma unroll
    for (int i = 0; i < 8; ++i)
#pragma unroll
        for (int j = 0; j < 8; ++j) acc[i][j] = 0.f;

    const float* Aptr = A + (size_t)(bm + lr) * K + lc;
    const float* Wptr = W + (size_t)(bn + lr) * K + lc;

    for (int k0 = 0; k0 < K; k0 += 8) {
        float4 av = *(const float4*)(Aptr + k0);
        float4 bv = *(const float4*)(Wptr + k0);
        As[lc + 0][lr] = av.x; As[lc + 1][lr] = av.y;
        As[lc + 2][lr] = av.z; As[lc + 3][lr] = av.w;
        Bs[lc + 0][lr] = bv.x; Bs[lc + 1][lr] = bv.y;
        Bs[lc + 2][lr] = bv.z; Bs[lc + 3][lr] = bv.w;
        __syncthreads();

#pragma unroll
        for (int kk = 0; kk < 8; ++kk) {
            float4 a0 = *(const float4*)&As[kk][ty * 8];
            float4 a1 = *(const float4*)&As[kk][ty * 8 + 4];
            float4 b0 = *(const float4*)&Bs[kk][tx * 8];
            float4 b1 = *(const float4*)&Bs[kk][tx * 8 + 4];
            float a[8] = {a0.x, a0.y, a0.z, a0.w, a1.x, a1.y, a1.z, a1.w};
            float b[8] = {b0.x, b0.y, b0.z, b0.w, b1.x, b1.y, b1.z, b1.w};
#pragma unroll
            for (int i = 0; i < 8; ++i)
#pragma unroll
                for (int j = 0; j < 8; ++j)
                    acc[i][j] = fmaf(a[i], b[j], acc[i][j]);
        }
        __syncthreads();
    }

#pragma unroll
    for (int i = 0; i < 8; ++i) {
        float* yrow = Y + (size_t)(bm + ty * 8 + i) * N + bn + tx * 8;
        *(float4*)(yrow + 0) = make_float4(acc[i][0], acc[i][1], acc[i][2], acc[i][3]);
        *(float4*)(yrow + 4) = make_float4(acc[i][4], acc[i][5], acc[i][6], acc[i][7]);
    }
}

__global__ void __launch_bounds__(256)
qkv_kernel(const float* __restrict__ x,
           const float* __restrict__ Wq,
           const float* __restrict__ Wk,
           const float* __restrict__ Wv) {
    const float* W;
    float* Y;
    if (blockIdx.z == 0)      { W = Wq; Y = g_q; }
    else if (blockIdx.z == 1) { W = Wk; Y = g_k; }
    else                      { W = Wv; Y = g_v; }
    gemm_nt_body(x, W, Y, HID, HID);
}

__global__ void __launch_bounds__(256)
proj_kernel(const float* __restrict__ Wo, float* __restrict__ out) {
    gemm_nt_body(g_att, Wo, out, HID, HID);
}

// ----------------------------------------------------------------------------
// Causal flash attention, fp32.
// One block per (q-tile of 64 rows, b*h). 256 threads as 16x16.
// Each thread: 4x4 of S, 4(rows)x4(dcols) of O.
// ----------------------------------------------------------------------------
#define SP 68                                   // padded tile row length
#define ATTN_SMEM ((4 * 64 * SP + 64 * 16) * 4) // 73728 bytes

__global__ void __launch_bounds__(256) attn_kernel() {
    extern __shared__ float sm[];
    float* QsT = sm;                // [kd][r]   64 x SP
    float* KsT = sm + 64 * SP;      // [kd][c]
    float* Vs  = sm + 2 * 64 * SP;  // [c][d]
    float* Ps  = sm + 3 * 64 * SP;  // [r][c]
    float* red = sm + 4 * 64 * SP;  // [row][tx] 64 x 16

    const int tid = threadIdx.x;
    const int ty = tid >> 4;        // 0..15
    const int tx = tid & 15;        // 0..15
    const int qt = blockIdx.x;      // q tile (0..31)
    const int bh = blockIdx.y;      // 0..31
    const int b  = bh >> 4;
    const int h  = bh & 15;
    const size_t headoff = (size_t)b * SEQ * HID + (size_t)h * HD;

    const int lrow = tid >> 4;      // 0..15 (per pass)
    const int ld4  = (tid & 15) * 4;

    // Load Q tile transposed: QsT[d][r]
#pragma unroll
    for (int p = 0; p < 4; ++p) {
        int r = p * 16 + lrow;
        float4 qv = *(const float4*)(g_q + headoff + (size_t)(qt * 64 + r) * HID + ld4);
        QsT[(ld4 + 0) * SP + r] = qv.x;
        QsT[(ld4 + 1) * SP + r] = qv.y;
        QsT[(ld4 + 2) * SP + r] = qv.z;
        QsT[(ld4 + 3) * SP + r] = qv.w;
    }

    float m[4], l[4], o[4][4];
#pragma unroll
    for (int i = 0; i < 4; ++i) {
        m[i] = -1e30f;
        l[i] = 0.f;
#pragma unroll
        for (int j = 0; j < 4; ++j) o[i][j] = 0.f;
    }

    for (int kt = 0; kt <= qt; ++kt) {
        // Load K tile (transposed) and V tile
#pragma unroll
        for (int p = 0; p < 4; ++p) {
            int r = p * 16 + lrow;
            size_t goff = headoff + (size_t)(kt * 64 + r) * HID + ld4;
            float4 kv = *(const float4*)(g_k + goff);
            KsT[(ld4 + 0) * SP + r] = kv.x;
            KsT[(ld4 + 1) * SP + r] = kv.y;
            KsT[(ld4 + 2) * SP + r] = kv.z;
            KsT[(ld4 + 3) * SP + r] = kv.w;
            float4 vv = *(const float4*)(g_v + goff);
            *(float4*)&Vs[r * SP + ld4] = vv;
        }
        __syncthreads();   // K/V (and, on first iter, Q) visible

        // S = Q K^T  (4x4 microtile)
        float s[4][4];
#pragma unroll
        for (int i = 0; i < 4; ++i)
#pragma unroll
            for (int j = 0; j < 4; ++j) s[i][j] = 0.f;

#pragma unroll 16
        for (int kd = 0; kd < 64; ++kd) {
            float4 qa = *(const float4*)&QsT[kd * SP + ty * 4];
            float4 kb = *(const float4*)&KsT[kd * SP + tx * 4];
            float a[4] = {qa.x, qa.y, qa.z, qa.w};
            float c[4] = {kb.x, kb.y, kb.z, kb.w};
#pragma unroll
            for (int i = 0; i < 4; ++i)
#pragma unroll
                for (int j = 0; j < 4; ++j)
                    s[i][j] = fmaf(a[i], c[j], s[i][j]);
        }

        const float scale = 0.125f;   // 1/sqrt(64)
#pragma unroll
        for (int i = 0; i < 4; ++i)
#pragma unroll
            for (int j = 0; j < 4; ++j) s[i][j] *= scale;

        if (kt == qt) {
            // causal mask on diagonal tile: col > row -> -inf
#pragma unroll
            for (int i = 0; i < 4; ++i)
#pragma unroll
                for (int j = 0; j < 4; ++j)
                    if (tx * 4 + j > ty * 4 + i) s[i][j] = -1e30f;
        }

        // row max partials
#pragma unroll
        for (int i = 0; i < 4; ++i) {
            float rm = fmaxf(fmaxf(s[i][0], s[i][1]), fmaxf(s[i][2], s[i][3]));
            red[(ty * 4 + i) * 16 + tx] = rm;
        }
        __syncthreads();

        float alpha[4];
#pragma unroll
        for (int i = 0; i < 4; ++i) {
            int row = ty * 4 + i;
            float mt = m[i];
#pragma unroll
            for (int t = 0; t < 16; ++t) mt = fmaxf(mt, red[row * 16 + t]);
            alpha[i] = __expf(m[i] - mt);
            m[i] = mt;
        }
        __syncthreads();   // everyone done reading red (maxes)

        // p = exp(s - m), stash to Ps, partial row sums to red
#pragma unroll
        for (int i = 0; i < 4; ++i) {
            float rs = 0.f;
#pragma unroll
            for (int j = 0; j < 4; ++j) {
                float p = __expf(s[i][j] - m[i]);
                Ps[(ty * 4 + i) * SP + tx * 4 + j] = p;
                rs += p;
            }
            red[(ty * 4 + i) * 16 + tx] = rs;
            // rescale running O
#pragma unroll
            for (int j = 0; j < 4; ++j) o[i][j] *= alpha[i];
        }
        __syncthreads();   // Ps + row-sum partials visible

#pragma unroll
        for (int i = 0; i < 4; ++i) {
            int row = ty * 4 + i;
            float su = 0.f;
#pragma unroll
            for (int t = 0; t < 16; ++t) su += red[row * 16 + t];
            l[i] = l[i] * alpha[i] + su;
        }

        // O += P @ V
#pragma unroll 8
        for (int c = 0; c < 64; ++c) {
            float4 vb = *(const float4*)&Vs[c * SP + tx * 4];
#pragma unroll
            for (int i = 0; i < 4; ++i) {
                float pv = Ps[(ty * 4 + i) * SP + c];
                o[i][0] = fmaf(pv, vb.x, o[i][0]);
                o[i][1] = fmaf(pv, vb.y, o[i][1]);
                o[i][2] = fmaf(pv, vb.z, o[i][2]);
                o[i][3] = fmaf(pv, vb.w, o[i][3]);
            }
        }
        __syncthreads();   // before next tile overwrites KsT/Vs/Ps
    }

    // epilogue: O /= l, write
#pragma unroll
    for (int i = 0; i < 4; ++i) {
        float inv = 1.f / l[i];
        int row = qt * 64 + ty * 4 + i;
        *(float4*)&g_att[headoff + (size_t)row * HID + tx * 4] =
            make_float4(o[i][0] * inv, o[i][1] * inv, o[i][2] * inv, o[i][3] * inv);
    }
}

// ----------------------------------------------------------------------------
extern "C" void kernel_launch(void* const* d_in, const int* in_sizes, int n_in,
                              void* d_out, int out_size) {
    const float* x  = (const float*)d_in[0];
    const float* Wq = (const float*)d_in[1];
    const float* Wk = (const float*)d_in[2];
    const float* Wv = (const float*)d_in[3];
    const float* Wo = (const float*)d_in[4];
    float* out = (float*)d_out;

    cudaFuncSetAttribute(attn_kernel,
                         cudaFuncAttributeMaxDynamicSharedMemorySize, ATTN_SMEM);

    dim3 gqkv(HID / 128, MROWS / 128, 3);   // 8 x 32 x 3
    qkv_kernel<<<gqkv, 256>>>(x, Wq, Wk, Wv);

    dim3 gattn(SEQ / 64, NB * NHEAD);       // 32 x 32
    attn_kernel<<<gattn, 256, ATTN_SMEM>>>();

    dim3 gproj(HID / 128, MROWS / 128);     // 8 x 32
    proj_kernel<<<gproj, 256>>>(Wo, out);
}

// round 7
// speedup vs baseline: 1.3055x; 1.3055x over previous
#include <cuda_runtime.h>
#include <cuda_bf16.h>
#include <cstdint>

#define HID 1024
#define NHEAD 16
#define HD 64
#define NB 2
#define SEQ 2048
#define MROWS (NB * SEQ)   // 4096

// Scratch (allocation-free rule: __device__ globals)
__device__ float g_q[MROWS * HID];
__device__ float g_k[MROWS * HID];
__device__ float g_v[MROWS * HID];
__device__ float g_att[MROWS * HID];

// ----------------------------------------------------------------------------
// tf32 tensor-core GEMM:  Y[M,N] = A[M,K] @ W[N,K]^T
// Both A and W are K-contiguous row-major (NT GEMM).
// 128x128 block tile, BK=32, 8 warps as 2(M) x 4(N), warp tile 64x32,
// mma.sync.aligned.m16n8k8.row.col tf32.
// ----------------------------------------------------------------------------
#define BM 128
#define BN 128
#define BKT 32
#define SPAD 132   // BM + 4

__device__ __forceinline__ uint32_t f2tf32(float x) {
    uint32_t r;
    asm("cvt.rna.tf32.f32 %0, %1;" : "=r"(r) : "f"(x));
    return r;
}

__device__ __forceinline__ void mma16n8k8(float* d, const uint32_t* a, const uint32_t* b) {
    asm volatile(
        "mma.sync.aligned.m16n8k8.row.col.f32.tf32.tf32.f32 "
        "{%0,%1,%2,%3}, {%4,%5,%6,%7}, {%8,%9}, {%0,%1,%2,%3};\n"
        : "+f"(d[0]), "+f"(d[1]), "+f"(d[2]), "+f"(d[3])
        : "r"(a[0]), "r"(a[1]), "r"(a[2]), "r"(a[3]),
          "r"(b[0]), "r"(b[1]));
}

__device__ __forceinline__ void gemm_nt_tc(const float* __restrict__ A,
                                           const float* __restrict__ W,
                                           float* __restrict__ Y,
                                           int K, int N) {
    __shared__ uint32_t As[BKT][SPAD];   // [k][m] tf32 bits
    __shared__ uint32_t Ws[BKT][SPAD];   // [k][n] tf32 bits

    const int tid  = threadIdx.x;
    const int lane = tid & 31;
    const int warp = tid >> 5;
    const int wm   = warp & 1;          // 0..1  -> 64-row slice
    const int wn   = warp >> 1;         // 0..3  -> 32-col slice
    const int g    = lane >> 2;         // 0..7
    const int t4   = lane & 3;          // 0..3

    const int bm = blockIdx.y * BM;
    const int bn = blockIdx.x * BN;

    // Loader mapping: thread handles one tile row, 16 contiguous k-floats.
    const int lr = tid & 127;           // tile row
    const int lc = (tid >> 7) * 16;     // k offset (0 or 16)

    const float* Aptr = A + (size_t)(bm + lr) * K + lc;
    const float* Wptr = W + (size_t)(bn + lr) * K + lc;

    float acc[4][4][4];
#pragma unroll
    for (int i = 0; i < 4; ++i)
#pragma unroll
        for (int j = 0; j < 4; ++j)
#pragma unroll
            for (int q = 0; q < 4; ++q) acc[i][j][q] = 0.f;

    for (int k0 = 0; k0 < K; k0 += BKT) {
        // stage tiles (transposed to [k][row]), converting to tf32
#pragma unroll
        for (int j = 0; j < 4; ++j) {
            float4 av = *(const float4*)(Aptr + k0 + j * 4);
            As[lc + j * 4 + 0][lr] = f2tf32(av.x);
            As[lc + j * 4 + 1][lr] = f2tf32(av.y);
            As[lc + j * 4 + 2][lr] = f2tf32(av.z);
            As[lc + j * 4 + 3][lr] = f2tf32(av.w);
            float4 wv = *(const float4*)(Wptr + k0 + j * 4);
            Ws[lc + j * 4 + 0][lr] = f2tf32(wv.x);
            Ws[lc + j * 4 + 1][lr] = f2tf32(wv.y);
            Ws[lc + j * 4 + 2][lr] = f2tf32(wv.z);
            Ws[lc + j * 4 + 3][lr] = f2tf32(wv.w);
        }
        __syncthreads();

#pragma unroll
        for (int ks = 0; ks < BKT; ks += 8) {
            uint32_t af[4][4];
            uint32_t bf[4][2];
#pragma unroll
            for (int mt = 0; mt < 4; ++mt) {
                int m0 = wm * 64 + mt * 16;
                af[mt][0] = As[ks + t4][m0 + g];
                af[mt][1] = As[ks + t4][m0 + g + 8];
                af[mt][2] = As[ks + t4 + 4][m0 + g];
                af[mt][3] = As[ks + t4 + 4][m0 + g + 8];
            }
#pragma unroll
            for (int nt = 0; nt < 4; ++nt) {
                int n0 = wn * 32 + nt * 8;
                bf[nt][0] = Ws[ks + t4][n0 + g];
                bf[nt][1] = Ws[ks + t4 + 4][n0 + g];
            }
#pragma unroll
            for (int mt = 0; mt < 4; ++mt)
#pragma unroll
                for (int nt = 0; nt < 4; ++nt)
                    mma16n8k8(acc[mt][nt], af[mt], bf[nt]);
        }
        __syncthreads();
    }

    // epilogue: c0,c1 -> (row g, col 2*t4 + {0,1}); c2,c3 -> row g+8
#pragma unroll
    for (int mt = 0; mt < 4; ++mt) {
        int r0 = bm + wm * 64 + mt * 16 + g;
#pragma unroll
        for (int nt = 0; nt < 4; ++nt) {
            int c = bn + wn * 32 + nt * 8 + 2 * t4;
            *(float2*)(Y + (size_t)r0 * N + c) =
                make_float2(acc[mt][nt][0], acc[mt][nt][1]);
            *(float2*)(Y + (size_t)(r0 + 8) * N + c) =
                make_float2(acc[mt][nt][2], acc[mt][nt][3]);
        }
    }
}

__global__ void __launch_bounds__(256, 2)
qkv_kernel(const float* __restrict__ x,
           const float* __restrict__ Wq,
           const float* __restrict__ Wk,
           const float* __restrict__ Wv) {
    const float* W;
    float* Y;
    if (blockIdx.z == 0)      { W = Wq; Y = g_q; }
    else if (blockIdx.z == 1) { W = Wk; Y = g_k; }
    else                      { W = Wv; Y = g_v; }
    gemm_nt_tc(x, W, Y, HID, HID);
}

__global__ void __launch_bounds__(256, 2)
proj_kernel(const float* __restrict__ Wo, float* __restrict__ out) {
    gemm_nt_tc(g_att, Wo, out, HID, HID);
}

// ----------------------------------------------------------------------------
// Causal flash attention, fp32 (unchanged from Round 0 baseline).
// ----------------------------------------------------------------------------
#define SP 68                                   // padded tile row length
#define ATTN_SMEM ((4 * 64 * SP + 64 * 16) * 4) // 73728 bytes

__global__ void __launch_bounds__(256) attn_kernel() {
    extern __shared__ float sm[];
    float* QsT = sm;                // [kd][r]   64 x SP
    float* KsT = sm + 64 * SP;      // [kd][c]
    float* Vs  = sm + 2 * 64 * SP;  // [c][d]
    float* Ps  = sm + 3 * 64 * SP;  // [r][c]
    float* red = sm + 4 * 64 * SP;  // [row][tx] 64 x 16

    const int tid = threadIdx.x;
    const int ty = tid >> 4;        // 0..15
    const int tx = tid & 15;        // 0..15
    const int qt = blockIdx.x;      // q tile (0..31)
    const int bh = blockIdx.y;      // 0..31
    const int b  = bh >> 4;
    const int h  = bh & 15;
    const size_t headoff = (size_t)b * SEQ * HID + (size_t)h * HD;

    const int lrow = tid >> 4;      // 0..15 (per pass)
    const int ld4  = (tid & 15) * 4;

    // Load Q tile transposed: QsT[d][r]
#pragma unroll
    for (int p = 0; p < 4; ++p) {
        int r = p * 16 + lrow;
        float4 qv = *(const float4*)(g_q + headoff + (size_t)(qt * 64 + r) * HID + ld4);
        QsT[(ld4 + 0) * SP + r] = qv.x;
        QsT[(ld4 + 1) * SP + r] = qv.y;
        QsT[(ld4 + 2) * SP + r] = qv.z;
        QsT[(ld4 + 3) * SP + r] = qv.w;
    }

    float m[4], l[4], o[4][4];
#pragma unroll
    for (int i = 0; i < 4; ++i) {
        m[i] = -1e30f;
        l[i] = 0.f;
#pragma unroll
        for (int j = 0; j < 4; ++j) o[i][j] = 0.f;
    }

    for (int kt = 0; kt <= qt; ++kt) {
        // Load K tile (transposed) and V tile
#pragma unroll
        for (int p = 0; p < 4; ++p) {
            int r = p * 16 + lrow;
            size_t goff = headoff + (size_t)(kt * 64 + r) * HID + ld4;
            float4 kv = *(const float4*)(g_k + goff);
            KsT[(ld4 + 0) * SP + r] = kv.x;
            KsT[(ld4 + 1) * SP + r] = kv.y;
            KsT[(ld4 + 2) * SP + r] = kv.z;
            KsT[(ld4 + 3) * SP + r] = kv.w;
            float4 vv = *(const float4*)(g_v + goff);
            *(float4*)&Vs[r * SP + ld4] = vv;
        }
        __syncthreads();   // K/V (and, on first iter, Q) visible

        // S = Q K^T  (4x4 microtile)
        float s[4][4];
#pragma unroll
        for (int i = 0; i < 4; ++i)
#pragma unroll
            for (int j = 0; j < 4; ++j) s[i][j] = 0.f;

#pragma unroll 16
        for (int kd = 0; kd < 64; ++kd) {
            float4 qa = *(const float4*)&QsT[kd * SP + ty * 4];
            float4 kb = *(const float4*)&KsT[kd * SP + tx * 4];
            float a[4] = {qa.x, qa.y, qa.z, qa.w};
            float c[4] = {kb.x, kb.y, kb.z, kb.w};
#pragma unroll
            for (int i = 0; i < 4; ++i)
#pragma unroll
                for (int j = 0; j < 4; ++j)
                    s[i][j] = fmaf(a[i], c[j], s[i][j]);
        }

        const float scale = 0.125f;   // 1/sqrt(64)
#pragma unroll
        for (int i = 0; i < 4; ++i)
#pragma unroll
            for (int j = 0; j < 4; ++j) s[i][j] *= scale;

        if (kt == qt) {
            // causal mask on diagonal tile: col > row -> -inf
#pragma unroll
            for (int i = 0; i < 4; ++i)
#pragma unroll
                for (int j = 0; j < 4; ++j)
                    if (tx * 4 + j > ty * 4 + i) s[i][j] = -1e30f;
        }

        // row max partials
#pragma unroll
        for (int i = 0; i < 4; ++i) {
            float rm = fmaxf(fmaxf(s[i][0], s[i][1]), fmaxf(s[i][2], s[i][3]));
            red[(ty * 4 + i) * 16 + tx] = rm;
        }
        __syncthreads();

        float alpha[4];
#pragma unroll
        for (int i = 0; i < 4; ++i) {
            int row = ty * 4 + i;
            float mt = m[i];
#pragma unroll
            for (int t = 0; t < 16; ++t) mt = fmaxf(mt, red[row * 16 + t]);
            alpha[i] = __expf(m[i] - mt);
            m[i] = mt;
        }
        __syncthreads();   // everyone done reading red (maxes)

        // p = exp(s - m), stash to Ps, partial row sums to red
#pragma unroll
        for (int i = 0; i < 4; ++i) {
            float rs = 0.f;
#pragma unroll
            for (int j = 0; j < 4; ++j) {
                float p = __expf(s[i][j] - m[i]);
                Ps[(ty * 4 + i) * SP + tx * 4 + j] = p;
                rs += p;
            }
            red[(ty * 4 + i) * 16 + tx] = rs;
            // rescale running O
#pragma unroll
            for (int j = 0; j < 4; ++j) o[i][j] *= alpha[i];
        }
        __syncthreads();   // Ps + row-sum partials visible

#pragma unroll
        for (int i = 0; i < 4; ++i) {
            int row = ty * 4 + i;
            float su = 0.f;
#pragma unroll
            for (int t = 0; t < 16; ++t) su += red[row * 16 + t];
            l[i] = l[i] * alpha[i] + su;
        }

        // O += P @ V
#pragma unroll 8
        for (int c = 0; c < 64; ++c) {
            float4 vb = *(const float4*)&Vs[c * SP + tx * 4];
#pragma unroll
            for (int i = 0; i < 4; ++i) {
                float pv = Ps[(ty * 4 + i) * SP + c];
                o[i][0] = fmaf(pv, vb.x, o[i][0]);
                o[i][1] = fmaf(pv, vb.y, o[i][1]);
                o[i][2] = fmaf(pv, vb.z, o[i][2]);
                o[i][3] = fmaf(pv, vb.w, o[i][3]);
            }
        }
        __syncthreads();   // before next tile overwrites KsT/Vs/Ps
    }

    // epilogue: O /= l, write
#pragma unroll
    for (int i = 0; i < 4; ++i) {
        float inv = 1.f / l[i];
        int row = qt * 64 + ty * 4 + i;
        *(float4*)&g_att[headoff + (size_t)row * HID + tx * 4] =
            make_float4(o[i][0] * inv, o[i][1] * inv, o[i][2] * inv, o[i][3] * inv);
    }
}

// ----------------------------------------------------------------------------
extern "C" void kernel_launch(void* const* d_in, const int* in_sizes, int n_in,
                              void* d_out, int out_size) {
    const float* x  = (const float*)d_in[0];
    const float* Wq = (const float*)d_in[1];
    const float* Wk = (const float*)d_in[2];
    const float* Wv = (const float*)d_in[3];
    const float* Wo = (const float*)d_in[4];
    float* out = (float*)d_out;

    cudaFuncSetAttribute(attn_kernel,
                         cudaFuncAttributeMaxDynamicSharedMemorySize, ATTN_SMEM);

    dim3 gqkv(HID / BN, MROWS / BM, 3);     // 8 x 32 x 3
    qkv_kernel<<<gqkv, 256>>>(x, Wq, Wk, Wv);

    dim3 gattn(SEQ / 64, NB * NHEAD);       // 32 x 32
    attn_kernel<<<gattn, 256, ATTN_SMEM>>>();

    dim3 gproj(HID / BN, MROWS / BM);       // 8 x 32
    proj_kernel<<<gproj, 256>>>(Wo, out);
}

// round 8
// speedup vs baseline: 1.9106x; 1.4635x over previous
#include <cuda_runtime.h>
#include <cuda_bf16.h>
#include <cstdint>

#define HID 1024
#define NHEAD 16
#define HD 64
#define NB 2
#define SEQ 2048
#define MROWS (NB * SEQ)   // 4096

// Scratch (allocation-free rule: __device__ globals)
__device__ float g_q[MROWS * HID];
__device__ float g_k[MROWS * HID];
__device__ float g_v[MROWS * HID];
__device__ float g_att[MROWS * HID];

__device__ __forceinline__ uint32_t f2tf32(float x) {
    uint32_t r;
    asm("cvt.rna.tf32.f32 %0, %1;" : "=r"(r) : "f"(x));
    return r;
}

__device__ __forceinline__ void mma16n8k8(float* d, const uint32_t* a, const uint32_t* b) {
    asm volatile(
        "mma.sync.aligned.m16n8k8.row.col.f32.tf32.tf32.f32 "
        "{%0,%1,%2,%3}, {%4,%5,%6,%7}, {%8,%9}, {%0,%1,%2,%3};\n"
        : "+f"(d[0]), "+f"(d[1]), "+f"(d[2]), "+f"(d[3])
        : "r"(a[0]), "r"(a[1]), "r"(a[2]), "r"(a[3]),
          "r"(b[0]), "r"(b[1]));
}

// ----------------------------------------------------------------------------
// tf32 tensor-core GEMM:  Y[M,N] = A[M,K] @ W[N,K]^T   (unchanged this round)
// ----------------------------------------------------------------------------
#define BM 128
#define BN 128
#define BKT 32
#define SPAD 132

__device__ __forceinline__ void gemm_nt_tc(const float* __restrict__ A,
                                           const float* __restrict__ W,
                                           float* __restrict__ Y,
                                           int K, int N) {
    __shared__ uint32_t As[BKT][SPAD];
    __shared__ uint32_t Ws[BKT][SPAD];

    const int tid  = threadIdx.x;
    const int lane = tid & 31;
    const int warp = tid >> 5;
    const int wm   = warp & 1;
    const int wn   = warp >> 1;
    const int g    = lane >> 2;
    const int t4   = lane & 3;

    const int bm = blockIdx.y * BM;
    const int bn = blockIdx.x * BN;

    const int lr = tid & 127;
    const int lc = (tid >> 7) * 16;

    const float* Aptr = A + (size_t)(bm + lr) * K + lc;
    const float* Wptr = W + (size_t)(bn + lr) * K + lc;

    float acc[4][4][4];
#pragma unroll
    for (int i = 0; i < 4; ++i)
#pragma unroll
        for (int j = 0; j < 4; ++j)
#pragma unroll
            for (int q = 0; q < 4; ++q) acc[i][j][q] = 0.f;

    for (int k0 = 0; k0 < K; k0 += BKT) {
#pragma unroll
        for (int j = 0; j < 4; ++j) {
            float4 av = *(const float4*)(Aptr + k0 + j * 4);
            As[lc + j * 4 + 0][lr] = f2tf32(av.x);
            As[lc + j * 4 + 1][lr] = f2tf32(av.y);
            As[lc + j * 4 + 2][lr] = f2tf32(av.z);
            As[lc + j * 4 + 3][lr] = f2tf32(av.w);
            float4 wv = *(const float4*)(Wptr + k0 + j * 4);
            Ws[lc + j * 4 + 0][lr] = f2tf32(wv.x);
            Ws[lc + j * 4 + 1][lr] = f2tf32(wv.y);
            Ws[lc + j * 4 + 2][lr] = f2tf32(wv.z);
            Ws[lc + j * 4 + 3][lr] = f2tf32(wv.w);
        }
        __syncthreads();

#pragma unroll
        for (int ks = 0; ks < BKT; ks += 8) {
            uint32_t af[4][4];
            uint32_t bf[4][2];
#pragma unroll
            for (int mt = 0; mt < 4; ++mt) {
                int m0 = wm * 64 + mt * 16;
                af[mt][0] = As[ks + t4][m0 + g];
                af[mt][1] = As[ks + t4][m0 + g + 8];
                af[mt][2] = As[ks + t4 + 4][m0 + g];
                af[mt][3] = As[ks + t4 + 4][m0 + g + 8];
            }
#pragma unroll
            for (int nt = 0; nt < 4; ++nt) {
                int n0 = wn * 32 + nt * 8;
                bf[nt][0] = Ws[ks + t4][n0 + g];
                bf[nt][1] = Ws[ks + t4 + 4][n0 + g];
            }
#pragma unroll
            for (int mt = 0; mt < 4; ++mt)
#pragma unroll
                for (int nt = 0; nt < 4; ++nt)
                    mma16n8k8(acc[mt][nt], af[mt], bf[nt]);
        }
        __syncthreads();
    }

#pragma unroll
    for (int mt = 0; mt < 4; ++mt) {
        int r0 = bm + wm * 64 + mt * 16 + g;
#pragma unroll
        for (int nt = 0; nt < 4; ++nt) {
            int c = bn + wn * 32 + nt * 8 + 2 * t4;
            *(float2*)(Y + (size_t)r0 * N + c) =
                make_float2(acc[mt][nt][0], acc[mt][nt][1]);
            *(float2*)(Y + (size_t)(r0 + 8) * N + c) =
                make_float2(acc[mt][nt][2], acc[mt][nt][3]);
        }
    }
}

__global__ void __launch_bounds__(256, 2)
qkv_kernel(const float* __restrict__ x,
           const float* __restrict__ Wq,
           const float* __restrict__ Wk,
           const float* __restrict__ Wv) {
    const float* W;
    float* Y;
    if (blockIdx.z == 0)      { W = Wq; Y = g_q; }
    else if (blockIdx.z == 1) { W = Wk; Y = g_k; }
    else                      { W = Wv; Y = g_v; }
    gemm_nt_tc(x, W, Y, HID, HID);
}

__global__ void __launch_bounds__(256, 2)
proj_kernel(const float* __restrict__ Wo, float* __restrict__ out) {
    gemm_nt_tc(g_att, Wo, out, HID, HID);
}

// ----------------------------------------------------------------------------
// Tensor-core causal flash attention (tf32 mma.sync).
// Block: 128 q-rows x (b,h). 8 warps, each owns 16 q-rows.
// K-tile = 64. All smem operands use k-axis permutation pi(b)=((b&3)<<1)|(b>>2)
// so fragment pairs (t4, t4+4) load as one LDS.64. Stride 72 floats.
// ----------------------------------------------------------------------------
#define AST 72
#define ATTN_SMEM (256 * AST * 4)   // Ks 64 + Vt 64 + Ps 128 rows = 73728 B

__device__ __forceinline__ int kperm(int d) {
    return (d & ~7) | (((d & 3) << 1) | ((d & 7) >> 2));
}

__global__ void __launch_bounds__(256, 1) attn_kernel() {
    extern __shared__ float sm[];
    float* Ks = sm;                 // [64][AST]  kv row, d col (pi on d)
    float* Vt = sm + 64 * AST;      // [64][AST]  d row, kv col (pi on kv)
    float* Ps = sm + 128 * AST;     // [128][AST] Q staging, then P (pi on kv-col)

    const int tid  = threadIdx.x;
    const int lane = tid & 31;
    const int w    = tid >> 5;
    const int g    = lane >> 2;
    const int t4   = lane & 3;

    const int qt = (int)gridDim.x - 1 - (int)blockIdx.x;  // heavy tiles first
    const int bh = blockIdx.y;
    const int b  = bh >> 4;
    const int h  = bh & 15;
    const size_t headoff = (size_t)b * SEQ * HID + (size_t)h * HD;
    const int qbase = qt * 128;

    // ---- stage Q (scaled by 1/8, tf32, pi on d) into Ps ----
    {
        int r  = tid >> 1;
        int c0 = (tid & 1) * 32;
        const float* qp = g_q + headoff + (size_t)(qbase + r) * HID + c0;
#pragma unroll
        for (int j = 0; j < 8; ++j) {
            float4 v = *(const float4*)(qp + j * 4);
            float vals[4] = {v.x, v.y, v.z, v.w};
#pragma unroll
            for (int i = 0; i < 4; ++i) {
                int d = c0 + j * 4 + i;
                Ps[r * AST + kperm(d)] = __uint_as_float(f2tf32(vals[i] * 0.125f));
            }
        }
    }
    __syncthreads();

    // ---- preload Q fragments (register resident) ----
    uint32_t qf[8][4];
#pragma unroll
    for (int ks = 0; ks < 8; ++ks) {
        float2 p0 = *(const float2*)&Ps[(w * 16 + g) * AST + ks * 8 + 2 * t4];
        float2 p1 = *(const float2*)&Ps[(w * 16 + g + 8) * AST + ks * 8 + 2 * t4];
        qf[ks][0] = __float_as_uint(p0.x);
        qf[ks][1] = __float_as_uint(p1.x);
        qf[ks][2] = __float_as_uint(p0.y);
        qf[ks][3] = __float_as_uint(p1.y);
    }
    __syncthreads();   // Q staging consumed; Ps becomes P

    float m0 = -1e30f, m1 = -1e30f, l0 = 0.f, l1 = 0.f;
    float oacc[8][4];
#pragma unroll
    for (int nt = 0; nt < 8; ++nt)
#pragma unroll
        for (int q = 0; q < 4; ++q) oacc[nt][q] = 0.f;

    const int row0 = qbase + w * 16 + g;
    const int row1 = row0 + 8;
    const int jc0 = (((2 * t4) & 3) << 1) | ((2 * t4) >> 2);
    const int jc1 = (((2 * t4 + 1) & 3) << 1) | ((2 * t4 + 1) >> 2);
    float* prow0 = &Ps[(w * 16 + g) * AST];
    float* prow1 = prow0 + 8 * AST;

    const int nkt = 2 * qt + 2;
    for (int kt = 0; kt < nkt; ++kt) {
        // ---- stage K tile ([kv][pi(d)]) and V transposed ([d][pi(kv)]) ----
        {
            int kvr = tid >> 2;
            int c0  = (tid & 3) * 16;
            const float* kp = g_k + headoff + (size_t)(kt * 64 + kvr) * HID + c0;
            const float* vp = g_v + headoff + (size_t)(kt * 64 + kvr) * HID + c0;
            int kvj = kperm(kvr);
#pragma unroll
            for (int j = 0; j < 4; ++j) {
                float4 kv4 = *(const float4*)(kp + j * 4);
                float4 vv4 = *(const float4*)(vp + j * 4);
                float kvals[4] = {kv4.x, kv4.y, kv4.z, kv4.w};
                float vvals[4] = {vv4.x, vv4.y, vv4.z, vv4.w};
#pragma unroll
                for (int i = 0; i < 4; ++i) {
                    int d = c0 + j * 4 + i;
                    Ks[kvr * AST + kperm(d)] = __uint_as_float(f2tf32(kvals[i]));
                    Vt[d * AST + kvj]        = __uint_as_float(f2tf32(vvals[i]));
                }
            }
        }
        __syncthreads();

        // ---- S = Q K^T ----
        float sacc[8][4];
#pragma unroll
        for (int nt = 0; nt < 8; ++nt)
#pragma unroll
            for (int q = 0; q < 4; ++q) sacc[nt][q] = 0.f;

#pragma unroll
        for (int nt = 0; nt < 8; ++nt) {
            const float* krow = &Ks[(nt * 8 + g) * AST + 2 * t4];
#pragma unroll
            for (int ks = 0; ks < 8; ++ks) {
                float2 bb = *(const float2*)(krow + ks * 8);
                uint32_t bf[2] = {__float_as_uint(bb.x), __float_as_uint(bb.y)};
                mma16n8k8(sacc[nt], qf[ks], bf);
            }
        }

        // ---- causal mask (only last two k-tiles can clip) ----
        if (kt >= 2 * qt) {
            int colb = kt * 64 + 2 * t4;
#pragma unroll
            for (int nt = 0; nt < 8; ++nt) {
                int c = colb + nt * 8;
                if (c     > row0) sacc[nt][0] = -1e30f;
                if (c + 1 > row0) sacc[nt][1] = -1e30f;
                if (c     > row1) sacc[nt][2] = -1e30f;
                if (c + 1 > row1) sacc[nt][3] = -1e30f;
            }
        }

        // ---- online softmax (quad shuffles; rows live in one quad) ----
        float mx0 = -1e30f, mx1 = -1e30f;
#pragma unroll
        for (int nt = 0; nt < 8; ++nt) {
            mx0 = fmaxf(mx0, fmaxf(sacc[nt][0], sacc[nt][1]));
            mx1 = fmaxf(mx1, fmaxf(sacc[nt][2], sacc[nt][3]));
        }
        mx0 = fmaxf(mx0, __shfl_xor_sync(0xffffffffu, mx0, 1));
        mx0 = fmaxf(mx0, __shfl_xor_sync(0xffffffffu, mx0, 2));
        mx1 = fmaxf(mx1, __shfl_xor_sync(0xffffffffu, mx1, 1));
        mx1 = fmaxf(mx1, __shfl_xor_sync(0xffffffffu, mx1, 2));

        float mn0 = fmaxf(m0, mx0), mn1 = fmaxf(m1, mx1);
        float al0 = __expf(m0 - mn0), al1 = __expf(m1 - mn1);
        m0 = mn0; m1 = mn1;

        float rs0 = 0.f, rs1 = 0.f;
#pragma unroll
        for (int nt = 0; nt < 8; ++nt) {
            float p00 = __expf(sacc[nt][0] - m0);
            float p01 = __expf(sacc[nt][1] - m0);
            float p10 = __expf(sacc[nt][2] - m1);
            float p11 = __expf(sacc[nt][3] - m1);
            rs0 += p00 + p01;
            rs1 += p10 + p11;
            prow0[nt * 8 + jc0] = __uint_as_float(f2tf32(p00));
            prow0[nt * 8 + jc1] = __uint_as_float(f2tf32(p01));
            prow1[nt * 8 + jc0] = __uint_as_float(f2tf32(p10));
            prow1[nt * 8 + jc1] = __uint_as_float(f2tf32(p11));
            oacc[nt][0] *= al0; oacc[nt][1] *= al0;
            oacc[nt][2] *= al1; oacc[nt][3] *= al1;
        }
        rs0 += __shfl_xor_sync(0xffffffffu, rs0, 1);
        rs0 += __shfl_xor_sync(0xffffffffu, rs0, 2);
        rs1 += __shfl_xor_sync(0xffffffffu, rs1, 1);
        rs1 += __shfl_xor_sync(0xffffffffu, rs1, 2);
        l0 = l0 * al0 + rs0;
        l1 = l1 * al1 + rs1;
        __syncwarp();   // P stores visible to own warp's fragment loads

        // ---- O += P V ----
#pragma unroll
        for (int ks = 0; ks < 8; ++ks) {
            float2 a02 = *(const float2*)(prow0 + ks * 8 + 2 * t4);
            float2 a13 = *(const float2*)(prow1 + ks * 8 + 2 * t4);
            uint32_t af[4] = {__float_as_uint(a02.x), __float_as_uint(a13.x),
                              __float_as_uint(a02.y), __float_as_uint(a13.y)};
#pragma unroll
            for (int nt = 0; nt < 8; ++nt) {
                float2 bb = *(const float2*)&Vt[(nt * 8 + g) * AST + ks * 8 + 2 * t4];
                uint32_t bf[2] = {__float_as_uint(bb.x), __float_as_uint(bb.y)};
                mma16n8k8(oacc[nt], af, bf);
            }
        }
        __syncthreads();   // protect Ks/Vt/Ps before next staging
    }

    // ---- epilogue ----
    float inv0 = 1.f / l0, inv1 = 1.f / l1;
    float* o0 = g_att + headoff + (size_t)(qbase + w * 16 + g) * HID;
    float* o1 = o0 + (size_t)8 * HID;
#pragma unroll
    for (int nt = 0; nt < 8; ++nt) {
        int c = nt * 8 + 2 * t4;
        *(float2*)(o0 + c) = make_float2(oacc[nt][0] * inv0, oacc[nt][1] * inv0);
        *(float2*)(o1 + c) = make_float2(oacc[nt][2] * inv1, oacc[nt][3] * inv1);
    }
}

// ----------------------------------------------------------------------------
extern "C" void kernel_launch(void* const* d_in, const int* in_sizes, int n_in,
                              void* d_out, int out_size) {
    const float* x  = (const float*)d_in[0];
    const float* Wq = (const float*)d_in[1];
    const float* Wk = (const float*)d_in[2];
    const float* Wv = (const float*)d_in[3];
    const float* Wo = (const float*)d_in[4];
    float* out = (float*)d_out;

    cudaFuncSetAttribute(attn_kernel,
                         cudaFuncAttributeMaxDynamicSharedMemorySize, ATTN_SMEM);

    dim3 gqkv(HID / BN, MROWS / BM, 3);     // 8 x 32 x 3
    qkv_kernel<<<gqkv, 256>>>(x, Wq, Wk, Wv);

    dim3 gattn(SEQ / 128, NB * NHEAD);      // 16 x 32
    attn_kernel<<<gattn, 256, ATTN_SMEM>>>();

    dim3 gproj(HID / BN, MROWS / BM);       // 8 x 32
    proj_kernel<<<gproj, 256>>>(Wo, out);
}

// round 9
// speedup vs baseline: 2.0228x; 1.0587x over previous
#include <cuda_runtime.h>
#include <cuda_bf16.h>
#include <cstdint>

#define HID 1024
#define NHEAD 16
#define HD 64
#define NB 2
#define SEQ 2048
#define MROWS (NB * SEQ)   // 4096

// Scratch (allocation-free rule: __device__ globals)
__device__ float g_q[MROWS * HID];
__device__ float g_k[MROWS * HID];
__device__ float g_v[MROWS * HID];
__device__ float g_att[MROWS * HID];

__device__ __forceinline__ uint32_t f2tf32(float x) {
    uint32_t r;
    asm("cvt.rna.tf32.f32 %0, %1;" : "=r"(r) : "f"(x));
    return r;
}

__device__ __forceinline__ void mma16n8k8(float* d, const uint32_t* a, const uint32_t* b) {
    asm volatile(
        "mma.sync.aligned.m16n8k8.row.col.f32.tf32.tf32.f32 "
        "{%0,%1,%2,%3}, {%4,%5,%6,%7}, {%8,%9}, {%0,%1,%2,%3};\n"
        : "+f"(d[0]), "+f"(d[1]), "+f"(d[2]), "+f"(d[3])
        : "r"(a[0]), "r"(a[1]), "r"(a[2]), "r"(a[3]),
          "r"(b[0]), "r"(b[1]));
}

// ----------------------------------------------------------------------------
// tf32 tensor-core GEMM:  Y[M,N] = A[M,K] @ W[N,K]^T
// 128x128 block tile, BK=16, register-prefetch double buffering.
// SPAD=136 (mod 32 == 8) -> fragment LDS across (t4 rows x g cols) hits all
// 32 banks exactly once: conflict-free.
// ----------------------------------------------------------------------------
#define BM 128
#define BN 128
#define BKT 16
#define SPAD 136

__device__ __forceinline__ void gemm_nt_tc(const float* __restrict__ A,
                                           const float* __restrict__ W,
                                           float* __restrict__ Y,
                                           int K, int N) {
    __shared__ uint32_t As[BKT][SPAD];
    __shared__ uint32_t Ws[BKT][SPAD];

    const int tid  = threadIdx.x;
    const int lane = tid & 31;
    const int warp = tid >> 5;
    const int wm   = warp & 1;          // 0..1 -> 64-row slice
    const int wn   = warp >> 1;         // 0..3 -> 32-col slice
    const int g    = lane >> 2;         // 0..7
    const int t4   = lane & 3;          // 0..3

    const int bm = blockIdx.y * BM;
    const int bn = blockIdx.x * BN;

    // Loader: thread handles one tile row, 8 contiguous k-floats.
    const int lr = tid & 127;           // tile row
    const int lc = (tid >> 7) * 8;      // k offset (0 or 8)

    const float* Aptr = A + (size_t)(bm + lr) * K + lc;
    const float* Wptr = W + (size_t)(bn + lr) * K + lc;

    float acc[4][4][4];
#pragma unroll
    for (int i = 0; i < 4; ++i)
#pragma unroll
        for (int j = 0; j < 4; ++j)
#pragma unroll
            for (int q = 0; q < 4; ++q) acc[i][j][q] = 0.f;

    // prefetch first tile
    float4 a0 = *(const float4*)(Aptr);
    float4 a1 = *(const float4*)(Aptr + 4);
    float4 w0 = *(const float4*)(Wptr);
    float4 w1 = *(const float4*)(Wptr + 4);

    for (int k0 = 0; k0 < K; k0 += BKT) {
        // stage prefetched regs (tf32, transposed [k][row])
        As[lc + 0][lr] = f2tf32(a0.x); As[lc + 1][lr] = f2tf32(a0.y);
        As[lc + 2][lr] = f2tf32(a0.z); As[lc + 3][lr] = f2tf32(a0.w);
        As[lc + 4][lr] = f2tf32(a1.x); As[lc + 5][lr] = f2tf32(a1.y);
        As[lc + 6][lr] = f2tf32(a1.z); As[lc + 7][lr] = f2tf32(a1.w);
        Ws[lc + 0][lr] = f2tf32(w0.x); Ws[lc + 1][lr] = f2tf32(w0.y);
        Ws[lc + 2][lr] = f2tf32(w0.z); Ws[lc + 3][lr] = f2tf32(w0.w);
        Ws[lc + 4][lr] = f2tf32(w1.x); Ws[lc + 5][lr] = f2tf32(w1.y);
        Ws[lc + 6][lr] = f2tf32(w1.z); Ws[lc + 7][lr] = f2tf32(w1.w);
        __syncthreads();

        // issue next tile's loads now; latency hidden by the MMA block below
        if (k0 + BKT < K) {
            a0 = *(const float4*)(Aptr + k0 + BKT);
            a1 = *(const float4*)(Aptr + k0 + BKT + 4);
            w0 = *(const float4*)(Wptr + k0 + BKT);
            w1 = *(const float4*)(Wptr + k0 + BKT + 4);
        }

#pragma unroll
        for (int ks = 0; ks < BKT; ks += 8) {
            uint32_t af[4][4];
            uint32_t bf[4][2];
#pragma unroll
            for (int mt = 0; mt < 4; ++mt) {
                int m0 = wm * 64 + mt * 16;
                af[mt][0] = As[ks + t4][m0 + g];
                af[mt][1] = As[ks + t4][m0 + g + 8];
                af[mt][2] = As[ks + t4 + 4][m0 + g];
                af[mt][3] = As[ks + t4 + 4][m0 + g + 8];
            }
#pragma unroll
            for (int nt = 0; nt < 4; ++nt) {
                int n0 = wn * 32 + nt * 8;
                bf[nt][0] = Ws[ks + t4][n0 + g];
                bf[nt][1] = Ws[ks + t4 + 4][n0 + g];
            }
#pragma unroll
            for (int mt = 0; mt < 4; ++mt)
#pragma unroll
                for (int nt = 0; nt < 4; ++nt)
                    mma16n8k8(acc[mt][nt], af[mt], bf[nt]);
        }
        __syncthreads();
    }

#pragma unroll
    for (int mt = 0; mt < 4; ++mt) {
        int r0 = bm + wm * 64 + mt * 16 + g;
#pragma unroll
        for (int nt = 0; nt < 4; ++nt) {
            int c = bn + wn * 32 + nt * 8 + 2 * t4;
            *(float2*)(Y + (size_t)r0 * N + c) =
                make_float2(acc[mt][nt][0], acc[mt][nt][1]);
            *(float2*)(Y + (size_t)(r0 + 8) * N + c) =
                make_float2(acc[mt][nt][2], acc[mt][nt][3]);
        }
    }
}

__global__ void __launch_bounds__(256, 2)
qkv_kernel(const float* __restrict__ x,
           const float* __restrict__ Wq,
           const float* __restrict__ Wk,
           const float* __restrict__ Wv) {
    const float* W;
    float* Y;
    if (blockIdx.z == 0)      { W = Wq; Y = g_q; }
    else if (blockIdx.z == 1) { W = Wk; Y = g_k; }
    else                      { W = Wv; Y = g_v; }
    gemm_nt_tc(x, W, Y, HID, HID);
}

__global__ void __launch_bounds__(256, 2)
proj_kernel(const float* __restrict__ Wo, float* __restrict__ out) {
    gemm_nt_tc(g_att, Wo, out, HID, HID);
}

// ----------------------------------------------------------------------------
// Tensor-core causal flash attention (tf32 mma.sync) — unchanged from R8.
// ----------------------------------------------------------------------------
#define AST 72
#define ATTN_SMEM (256 * AST * 4)   // 73728 B

__device__ __forceinline__ int kperm(int d) {
    return (d & ~7) | (((d & 3) << 1) | ((d & 7) >> 2));
}

__global__ void __launch_bounds__(256, 1) attn_kernel() {
    extern __shared__ float sm[];
    float* Ks = sm;                 // [64][AST]  kv row, d col (pi on d)
    float* Vt = sm + 64 * AST;      // [64][AST]  d row, kv col (pi on kv)
    float* Ps = sm + 128 * AST;     // [128][AST] Q staging, then P

    const int tid  = threadIdx.x;
    const int lane = tid & 31;
    const int w    = tid >> 5;
    const int g    = lane >> 2;
    const int t4   = lane & 3;

    const int qt = (int)gridDim.x - 1 - (int)blockIdx.x;  // heavy tiles first
    const int bh = blockIdx.y;
    const int b  = bh >> 4;
    const int h  = bh & 15;
    const size_t headoff = (size_t)b * SEQ * HID + (size_t)h * HD;
    const int qbase = qt * 128;

    // ---- stage Q (scaled by 1/8, tf32, pi on d) into Ps ----
    {
        int r  = tid >> 1;
        int c0 = (tid & 1) * 32;
        const float* qp = g_q + headoff + (size_t)(qbase + r) * HID + c0;
#pragma unroll
        for (int j = 0; j < 8; ++j) {
            float4 v = *(const float4*)(qp + j * 4);
            float vals[4] = {v.x, v.y, v.z, v.w};
#pragma unroll
            for (int i = 0; i < 4; ++i) {
                int d = c0 + j * 4 + i;
                Ps[r * AST + kperm(d)] = __uint_as_float(f2tf32(vals[i] * 0.125f));
            }
        }
    }
    __syncthreads();

    // ---- preload Q fragments (register resident) ----
    uint32_t qf[8][4];
#pragma unroll
    for (int ks = 0; ks < 8; ++ks) {
        float2 p0 = *(const float2*)&Ps[(w * 16 + g) * AST + ks * 8 + 2 * t4];
        float2 p1 = *(const float2*)&Ps[(w * 16 + g + 8) * AST + ks * 8 + 2 * t4];
        qf[ks][0] = __float_as_uint(p0.x);
        qf[ks][1] = __float_as_uint(p1.x);
        qf[ks][2] = __float_as_uint(p0.y);
        qf[ks][3] = __float_as_uint(p1.y);
    }
    __syncthreads();   // Q staging consumed; Ps becomes P

    float m0 = -1e30f, m1 = -1e30f, l0 = 0.f, l1 = 0.f;
    float oacc[8][4];
#pragma unroll
    for (int nt = 0; nt < 8; ++nt)
#pragma unroll
        for (int q = 0; q < 4; ++q) oacc[nt][q] = 0.f;

    const int row0 = qbase + w * 16 + g;
    const int row1 = row0 + 8;
    const int jc0 = (((2 * t4) & 3) << 1) | ((2 * t4) >> 2);
    const int jc1 = (((2 * t4 + 1) & 3) << 1) | ((2 * t4 + 1) >> 2);
    float* prow0 = &Ps[(w * 16 + g) * AST];
    float* prow1 = prow0 + 8 * AST;

    const int nkt = 2 * qt + 2;
    for (int kt = 0; kt < nkt; ++kt) {
        // ---- stage K tile ([kv][pi(d)]) and V transposed ([d][pi(kv)]) ----
        {
            int kvr = tid >> 2;
            int c0  = (tid & 3) * 16;
            const float* kp = g_k + headoff + (size_t)(kt * 64 + kvr) * HID + c0;
            const float* vp = g_v + headoff + (size_t)(kt * 64 + kvr) * HID + c0;
            int kvj = kperm(kvr);
#pragma unroll
            for (int j = 0; j < 4; ++j) {
                float4 kv4 = *(const float4*)(kp + j * 4);
                float4 vv4 = *(const float4*)(vp + j * 4);
                float kvals[4] = {kv4.x, kv4.y, kv4.z, kv4.w};
                float vvals[4] = {vv4.x, vv4.y, vv4.z, vv4.w};
#pragma unroll
                for (int i = 0; i < 4; ++i) {
                    int d = c0 + j * 4 + i;
                    Ks[kvr * AST + kperm(d)] = __uint_as_float(f2tf32(kvals[i]));
                    Vt[d * AST + kvj]        = __uint_as_float(f2tf32(vvals[i]));
                }
            }
        }
        __syncthreads();

        // ---- S = Q K^T ----
        float sacc[8][4];
#pragma unroll
        for (int nt = 0; nt < 8; ++nt)
#pragma unroll
            for (int q = 0; q < 4; ++q) sacc[nt][q] = 0.f;

#pragma unroll
        for (int nt = 0; nt < 8; ++nt) {
            const float* krow = &Ks[(nt * 8 + g) * AST + 2 * t4];
#pragma unroll
            for (int ks = 0; ks < 8; ++ks) {
                float2 bb = *(const float2*)(krow + ks * 8);
                uint32_t bf[2] = {__float_as_uint(bb.x), __float_as_uint(bb.y)};
                mma16n8k8(sacc[nt], qf[ks], bf);
            }
        }

        // ---- causal mask (only last two k-tiles can clip) ----
        if (kt >= 2 * qt) {
            int colb = kt * 64 + 2 * t4;
#pragma unroll
            for (int nt = 0; nt < 8; ++nt) {
                int c = colb + nt * 8;
                if (c     > row0) sacc[nt][0] = -1e30f;
                if (c + 1 > row0) sacc[nt][1] = -1e30f;
                if (c     > row1) sacc[nt][2] = -1e30f;
                if (c + 1 > row1) sacc[nt][3] = -1e30f;
            }
        }

        // ---- online softmax (quad shuffles) ----
        float mx0 = -1e30f, mx1 = -1e30f;
#pragma unroll
        for (int nt = 0; nt < 8; ++nt) {
            mx0 = fmaxf(mx0, fmaxf(sacc[nt][0], sacc[nt][1]));
            mx1 = fmaxf(mx1, fmaxf(sacc[nt][2], sacc[nt][3]));
        }
        mx0 = fmaxf(mx0, __shfl_xor_sync(0xffffffffu, mx0, 1));
        mx0 = fmaxf(mx0, __shfl_xor_sync(0xffffffffu, mx0, 2));
        mx1 = fmaxf(mx1, __shfl_xor_sync(0xffffffffu, mx1, 1));
        mx1 = fmaxf(mx1, __shfl_xor_sync(0xffffffffu, mx1, 2));

        float mn0 = fmaxf(m0, mx0), mn1 = fmaxf(m1, mx1);
        float al0 = __expf(m0 - mn0), al1 = __expf(m1 - mn1);
        m0 = mn0; m1 = mn1;

        float rs0 = 0.f, rs1 = 0.f;
#pragma unroll
        for (int nt = 0; nt < 8; ++nt) {
            float p00 = __expf(sacc[nt][0] - m0);
            float p01 = __expf(sacc[nt][1] - m0);
            float p10 = __expf(sacc[nt][2] - m1);
            float p11 = __expf(sacc[nt][3] - m1);
            rs0 += p00 + p01;
            rs1 += p10 + p11;
            prow0[nt * 8 + jc0] = __uint_as_float(f2tf32(p00));
            prow0[nt * 8 + jc1] = __uint_as_float(f2tf32(p01));
            prow1[nt * 8 + jc0] = __uint_as_float(f2tf32(p10));
            prow1[nt * 8 + jc1] = __uint_as_float(f2tf32(p11));
            oacc[nt][0] *= al0; oacc[nt][1] *= al0;
            oacc[nt][2] *= al1; oacc[nt][3] *= al1;
        }
        rs0 += __shfl_xor_sync(0xffffffffu, rs0, 1);
        rs0 += __shfl_xor_sync(0xffffffffu, rs0, 2);
        rs1 += __shfl_xor_sync(0xffffffffu, rs1, 1);
        rs1 += __shfl_xor_sync(0xffffffffu, rs1, 2);
        l0 = l0 * al0 + rs0;
        l1 = l1 * al1 + rs1;
        __syncwarp();   // P stores visible to own warp's fragment loads

        // ---- O += P V ----
#pragma unroll
        for (int ks = 0; ks < 8; ++ks) {
            float2 a02 = *(const float2*)(prow0 + ks * 8 + 2 * t4);
            float2 a13 = *(const float2*)(prow1 + ks * 8 + 2 * t4);
            uint32_t af[4] = {__float_as_uint(a02.x), __float_as_uint(a13.x),
                              __float_as_uint(a02.y), __float_as_uint(a13.y)};
#pragma unroll
            for (int nt = 0; nt < 8; ++nt) {
                float2 bb = *(const float2*)&Vt[(nt * 8 + g) * AST + ks * 8 + 2 * t4];
                uint32_t bf[2] = {__float_as_uint(bb.x), __float_as_uint(bb.y)};
                mma16n8k8(oacc[nt], af, bf);
            }
        }
        __syncthreads();   // protect Ks/Vt/Ps before next staging
    }

    // ---- epilogue ----
    float inv0 = 1.f / l0, inv1 = 1.f / l1;
    float* o0 = g_att + headoff + (size_t)(qbase + w * 16 + g) * HID;
    float* o1 = o0 + (size_t)8 * HID;
#pragma unroll
    for (int nt = 0; nt < 8; ++nt) {
        int c = nt * 8 + 2 * t4;
        *(float2*)(o0 + c) = make_float2(oacc[nt][0] * inv0, oacc[nt][1] * inv0);
        *(float2*)(o1 + c) = make_float2(oacc[nt][2] * inv1, oacc[nt][3] * inv1);
    }
}

// ----------------------------------------------------------------------------
extern "C" void kernel_launch(void* const* d_in, const int* in_sizes, int n_in,
                              void* d_out, int out_size) {
    const float* x  = (const float*)d_in[0];
    const float* Wq = (const float*)d_in[1];
    const float* Wk = (const float*)d_in[2];
    const float* Wv = (const float*)d_in[3];
    const float* Wo = (const float*)d_in[4];
    float* out = (float*)d_out;

    cudaFuncSetAttribute(attn_kernel,
                         cudaFuncAttributeMaxDynamicSharedMemorySize, ATTN_SMEM);

    dim3 gqkv(HID / BN, MROWS / BM, 3);     // 8 x 32 x 3
    qkv_kernel<<<gqkv, 256>>>(x, Wq, Wk, Wv);

    dim3 gattn(SEQ / 128, NB * NHEAD);      // 16 x 32
    attn_kernel<<<gattn, 256, ATTN_SMEM>>>();

    dim3 gproj(HID / BN, MROWS / BM);       // 8 x 32
    proj_kernel<<<gproj, 256>>>(Wo, out);
}

// round 10
// speedup vs baseline: 2.7028x; 1.3362x over previous
#include <cuda_runtime.h>
#include <cuda_bf16.h>
#include <cstdint>

#define HID 1024
#define NHEAD 16
#define HD 64
#define NB 2
#define SEQ 2048
#define MROWS (NB * SEQ)   // 4096

// Scratch (allocation-free rule: __device__ globals)
__device__ float g_q[MROWS * HID];
__device__ float g_k[MROWS * HID];
__device__ float g_v[MROWS * HID];
__device__ float g_att[MROWS * HID];

__device__ __forceinline__ uint32_t f2tf32(float x) {
    uint32_t r;
    asm("cvt.rna.tf32.f32 %0, %1;" : "=r"(r) : "f"(x));
    return r;
}

__device__ __forceinline__ void mma16n8k8(float* d, const uint32_t* a, const uint32_t* b) {
    asm volatile(
        "mma.sync.aligned.m16n8k8.row.col.f32.tf32.tf32.f32 "
        "{%0,%1,%2,%3}, {%4,%5,%6,%7}, {%8,%9}, {%0,%1,%2,%3};\n"
        : "+f"(d[0]), "+f"(d[1]), "+f"(d[2]), "+f"(d[3])
        : "r"(a[0]), "r"(a[1]), "r"(a[2]), "r"(a[3]),
          "r"(b[0]), "r"(b[1]));
}

// ----------------------------------------------------------------------------
// tf32 tensor-core GEMM:  Y[M,N] = A[M,K] @ W[N,K]^T
// 128x128 block tile, BK=16, register-prefetch double buffering.
// m-major smem [row][ST=24] with k-pair interleave + XOR swizzle:
//   word pos(k') = (2*(k'&3) + (k'>>2)) ^ e(m),  e(m)=(((m&1)<<1)|((m>>2)&1))<<1
// -> fragment pairs (k=t4, k=t4+4) load as a single LDS.64, conflict-free;
//    staging is STS.64, conflict-free; loader lr=tid>>1 halves L1 lines/LDG.
// ----------------------------------------------------------------------------
#define BM 128
#define BN 128
#define BKT 16
#define ST 24

__device__ __forceinline__ int eswz(int m) {
    return (((m & 1) << 1) | ((m >> 2) & 1)) << 1;
}

__device__ __forceinline__ void gemm_nt_tc(const float* __restrict__ A,
                                           const float* __restrict__ W,
                                           float* __restrict__ Y,
                                           int K, int N) {
    __shared__ uint32_t As[BM][ST];
    __shared__ uint32_t Ws[BN][ST];

    const int tid  = threadIdx.x;
    const int lane = tid & 31;
    const int warp = tid >> 5;
    const int wm   = warp & 1;          // 0..1 -> 64-row slice
    const int wn   = warp >> 1;         // 0..3 -> 32-col slice
    const int g    = lane >> 2;         // 0..7
    const int t4   = lane & 3;          // 0..3

    const int bm = blockIdx.y * BM;
    const int bn = blockIdx.x * BN;

    // Loader: two lanes per row; lane covers 8 contiguous k-floats (one ksb group).
    const int lr   = tid >> 1;          // 0..127 tile row
    const int half = tid & 1;           // ksb group (0: k0-7, 1: k8-15)
    const int lc   = half * 8;

    const float* Aptr = A + (size_t)(bm + lr) * K + lc;
    const float* Wptr = W + (size_t)(bn + lr) * K + lc;

    const int se = eswz(lr);
    uint32_t* arow = &As[lr][half * 8];
    uint32_t* wrow = &Ws[lr][half * 8];

    float acc[4][4][4];
#pragma unroll
    for (int i = 0; i < 4; ++i)
#pragma unroll
        for (int j = 0; j < 4; ++j)
#pragma unroll
            for (int q = 0; q < 4; ++q) acc[i][j][q] = 0.f;

    // prefetch first tile (8 floats per array per thread)
    float4 a0 = *(const float4*)(Aptr);
    float4 a1 = *(const float4*)(Aptr + 4);
    float4 w0 = *(const float4*)(Wptr);
    float4 w1 = *(const float4*)(Wptr + 4);

    for (int k0 = 0; k0 < K; k0 += BKT) {
        // stage prefetched regs as tf32 k-pairs (j, j+4) -> STS.64
        *(uint2*)&arow[0 ^ se] = make_uint2(f2tf32(a0.x), f2tf32(a1.x));
        *(uint2*)&arow[2 ^ se] = make_uint2(f2tf32(a0.y), f2tf32(a1.y));
        *(uint2*)&arow[4 ^ se] = make_uint2(f2tf32(a0.z), f2tf32(a1.z));
        *(uint2*)&arow[6 ^ se] = make_uint2(f2tf32(a0.w), f2tf32(a1.w));
        *(uint2*)&wrow[0 ^ se] = make_uint2(f2tf32(w0.x), f2tf32(w1.x));
        *(uint2*)&wrow[2 ^ se] = make_uint2(f2tf32(w0.y), f2tf32(w1.y));
        *(uint2*)&wrow[4 ^ se] = make_uint2(f2tf32(w0.z), f2tf32(w1.z));
        *(uint2*)&wrow[6 ^ se] = make_uint2(f2tf32(w0.w), f2tf32(w1.w));
        __syncthreads();

        // issue next tile's loads now; latency hidden by the MMA block below
        if (k0 + BKT < K) {
            a0 = *(const float4*)(Aptr + k0 + BKT);
            a1 = *(const float4*)(Aptr + k0 + BKT + 4);
            w0 = *(const float4*)(Wptr + k0 + BKT);
            w1 = *(const float4*)(Wptr + k0 + BKT + 4);
        }

#pragma unroll
        for (int ksb = 0; ksb < 2; ++ksb) {
            uint32_t af[4][4];
            uint32_t bf[4][2];
#pragma unroll
            for (int mt = 0; mt < 4; ++mt) {
                int r0 = wm * 64 + mt * 16 + g;
                int em = eswz(r0);                 // same for r0 and r0+8
                uint2 p = *(const uint2*)&As[r0][ksb * 8 + (2 * t4 ^ em)];
                uint2 q = *(const uint2*)&As[r0 + 8][ksb * 8 + (2 * t4 ^ em)];
                af[mt][0] = p.x; af[mt][1] = q.x;
                af[mt][2] = p.y; af[mt][3] = q.y;
            }
#pragma unroll
            for (int nt = 0; nt < 4; ++nt) {
                int n0 = wn * 32 + nt * 8 + g;
                int en = eswz(n0);
                uint2 r = *(const uint2*)&Ws[n0][ksb * 8 + (2 * t4 ^ en)];
                bf[nt][0] = r.x; bf[nt][1] = r.y;
            }
#pragma unroll
            for (int mt = 0; mt < 4; ++mt)
#pragma unroll
                for (int nt = 0; nt < 4; ++nt)
                    mma16n8k8(acc[mt][nt], af[mt], bf[nt]);
        }
        __syncthreads();
    }

#pragma unroll
    for (int mt = 0; mt < 4; ++mt) {
        int r0 = bm + wm * 64 + mt * 16 + g;
#pragma unroll
        for (int nt = 0; nt < 4; ++nt) {
            int c = bn + wn * 32 + nt * 8 + 2 * t4;
            *(float2*)(Y + (size_t)r0 * N + c) =
                make_float2(acc[mt][nt][0], acc[mt][nt][1]);
            *(float2*)(Y + (size_t)(r0 + 8) * N + c) =
                make_float2(acc[mt][nt][2], acc[mt][nt][3]);
        }
    }
}

__global__ void __launch_bounds__(256, 2)
qkv_kernel(const float* __restrict__ x,
           const float* __restrict__ Wq,
           const float* __restrict__ Wk,
           const float* __restrict__ Wv) {
    const float* W;
    float* Y;
    if (blockIdx.z == 0)      { W = Wq; Y = g_q; }
    else if (blockIdx.z == 1) { W = Wk; Y = g_k; }
    else                      { W = Wv; Y = g_v; }
    gemm_nt_tc(x, W, Y, HID, HID);
}

__global__ void __launch_bounds__(256, 2)
proj_kernel(const float* __restrict__ Wo, float* __restrict__ out) {
    gemm_nt_tc(g_att, Wo, out, HID, HID);
}

// ----------------------------------------------------------------------------
// Tensor-core causal flash attention (tf32 mma.sync) — unchanged from R8/R9.
// ----------------------------------------------------------------------------
#define AST 72
#define ATTN_SMEM (256 * AST * 4)   // 73728 B

__device__ __forceinline__ int kperm(int d) {
    return (d & ~7) | (((d & 3) << 1) | ((d & 7) >> 2));
}

__global__ void __launch_bounds__(256, 1) attn_kernel() {
    extern __shared__ float sm[];
    float* Ks = sm;                 // [64][AST]  kv row, d col (pi on d)
    float* Vt = sm + 64 * AST;      // [64][AST]  d row, kv col (pi on kv)
    float* Ps = sm + 128 * AST;     // [128][AST] Q staging, then P

    const int tid  = threadIdx.x;
    const int lane = tid & 31;
    const int w    = tid >> 5;
    const int g    = lane >> 2;
    const int t4   = lane & 3;

    const int qt = (int)gridDim.x - 1 - (int)blockIdx.x;  // heavy tiles first
    const int bh = blockIdx.y;
    const int b  = bh >> 4;
    const int h  = bh & 15;
    const size_t headoff = (size_t)b * SEQ * HID + (size_t)h * HD;
    const int qbase = qt * 128;

    // ---- stage Q (scaled by 1/8, tf32, pi on d) into Ps ----
    {
        int r  = tid >> 1;
        int c0 = (tid & 1) * 32;
        const float* qp = g_q + headoff + (size_t)(qbase + r) * HID + c0;
#pragma unroll
        for (int j = 0; j < 8; ++j) {
            float4 v = *(const float4*)(qp + j * 4);
            float vals[4] = {v.x, v.y, v.z, v.w};
#pragma unroll
            for (int i = 0; i < 4; ++i) {
                int d = c0 + j * 4 + i;
                Ps[r * AST + kperm(d)] = __uint_as_float(f2tf32(vals[i] * 0.125f));
            }
        }
    }
    __syncthreads();

    // ---- preload Q fragments (register resident) ----
    uint32_t qf[8][4];
#pragma unroll
    for (int ks = 0; ks < 8; ++ks) {
        float2 p0 = *(const float2*)&Ps[(w * 16 + g) * AST + ks * 8 + 2 * t4];
        float2 p1 = *(const float2*)&Ps[(w * 16 + g + 8) * AST + ks * 8 + 2 * t4];
        qf[ks][0] = __float_as_uint(p0.x);
        qf[ks][1] = __float_as_uint(p1.x);
        qf[ks][2] = __float_as_uint(p0.y);
        qf[ks][3] = __float_as_uint(p1.y);
    }
    __syncthreads();   // Q staging consumed; Ps becomes P

    float m0 = -1e30f, m1 = -1e30f, l0 = 0.f, l1 = 0.f;
    float oacc[8][4];
#pragma unroll
    for (int nt = 0; nt < 8; ++nt)
#pragma unroll
        for (int q = 0; q < 4; ++q) oacc[nt][q] = 0.f;

    const int row0 = qbase + w * 16 + g;
    const int row1 = row0 + 8;
    const int jc0 = (((2 * t4) & 3) << 1) | ((2 * t4) >> 2);
    const int jc1 = (((2 * t4 + 1) & 3) << 1) | ((2 * t4 + 1) >> 2);
    float* prow0 = &Ps[(w * 16 + g) * AST];
    float* prow1 = prow0 + 8 * AST;

    const int nkt = 2 * qt + 2;
    for (int kt = 0; kt < nkt; ++kt) {
        // ---- stage K tile ([kv][pi(d)]) and V transposed ([d][pi(kv)]) ----
        {
            int kvr = tid >> 2;
            int c0  = (tid & 3) * 16;
            const float* kp = g_k + headoff + (size_t)(kt * 64 + kvr) * HID + c0;
            const float* vp = g_v + headoff + (size_t)(kt * 64 + kvr) * HID + c0;
            int kvj = kperm(kvr);
#pragma unroll
            for (int j = 0; j < 4; ++j) {
                float4 kv4 = *(const float4*)(kp + j * 4);
                float4 vv4 = *(const float4*)(vp + j * 4);
                float kvals[4] = {kv4.x, kv4.y, kv4.z, kv4.w};
                float vvals[4] = {vv4.x, vv4.y, vv4.z, vv4.w};
#pragma unroll
                for (int i = 0; i < 4; ++i) {
                    int d = c0 + j * 4 + i;
                    Ks[kvr * AST + kperm(d)] = __uint_as_float(f2tf32(kvals[i]));
                    Vt[d * AST + kvj]        = __uint_as_float(f2tf32(vvals[i]));
                }
            }
        }
        __syncthreads();

        // ---- S = Q K^T ----
        float sacc[8][4];
#pragma unroll
        for (int nt = 0; nt < 8; ++nt)
#pragma unroll
            for (int q = 0; q < 4; ++q) sacc[nt][q] = 0.f;

#pragma unroll
        for (int nt = 0; nt < 8; ++nt) {
            const float* krow = &Ks[(nt * 8 + g) * AST + 2 * t4];
#pragma unroll
            for (int ks = 0; ks < 8; ++ks) {
                float2 bb = *(const float2*)(krow + ks * 8);
                uint32_t bf[2] = {__float_as_uint(bb.x), __float_as_uint(bb.y)};
                mma16n8k8(sacc[nt], qf[ks], bf);
            }
        }

        // ---- causal mask (only last two k-tiles can clip) ----
        if (kt >= 2 * qt) {
            int colb = kt * 64 + 2 * t4;
#pragma unroll
            for (int nt = 0; nt < 8; ++nt) {
                int c = colb + nt * 8;
                if (c     > row0) sacc[nt][0] = -1e30f;
                if (c + 1 > row0) sacc[nt][1] = -1e30f;
                if (c     > row1) sacc[nt][2] = -1e30f;
                if (c + 1 > row1) sacc[nt][3] = -1e30f;
            }
        }

        // ---- online softmax (quad shuffles) ----
        float mx0 = -1e30f, mx1 = -1e30f;
#pragma unroll
        for (int nt = 0; nt < 8; ++nt) {
            mx0 = fmaxf(mx0, fmaxf(sacc[nt][0], sacc[nt][1]));
            mx1 = fmaxf(mx1, fmaxf(sacc[nt][2], sacc[nt][3]));
        }
        mx0 = fmaxf(mx0, __shfl_xor_sync(0xffffffffu, mx0, 1));
        mx0 = fmaxf(mx0, __shfl_xor_sync(0xffffffffu, mx0, 2));
        mx1 = fmaxf(mx1, __shfl_xor_sync(0xffffffffu, mx1, 1));
        mx1 = fmaxf(mx1, __shfl_xor_sync(0xffffffffu, mx1, 2));

        float mn0 = fmaxf(m0, mx0), mn1 = fmaxf(m1, mx1);
        float al0 = __expf(m0 - mn0), al1 = __expf(m1 - mn1);
        m0 = mn0; m1 = mn1;

        float rs0 = 0.f, rs1 = 0.f;
#pragma unroll
        for (int nt = 0; nt < 8; ++nt) {
            float p00 = __expf(sacc[nt][0] - m0);
            float p01 = __expf(sacc[nt][1] - m0);
            float p10 = __expf(sacc[nt][2] - m1);
            float p11 = __expf(sacc[nt][3] - m1);
            rs0 += p00 + p01;
            rs1 += p10 + p11;
            prow0[nt * 8 + jc0] = __uint_as_float(f2tf32(p00));
            prow0[nt * 8 + jc1] = __uint_as_float(f2tf32(p01));
            prow1[nt * 8 + jc0] = __uint_as_float(f2tf32(p10));
            prow1[nt * 8 + jc1] = __uint_as_float(f2tf32(p11));
            oacc[nt][0] *= al0; oacc[nt][1] *= al0;
            oacc[nt][2] *= al1; oacc[nt][3] *= al1;
        }
        rs0 += __shfl_xor_sync(0xffffffffu, rs0, 1);
        rs0 += __shfl_xor_sync(0xffffffffu, rs0, 2);
        rs1 += __shfl_xor_sync(0xffffffffu, rs1, 1);
        rs1 += __shfl_xor_sync(0xffffffffu, rs1, 2);
        l0 = l0 * al0 + rs0;
        l1 = l1 * al1 + rs1;
        __syncwarp();   // P stores visible to own warp's fragment loads

        // ---- O += P V ----
#pragma unroll
        for (int ks = 0; ks < 8; ++ks) {
            float2 a02 = *(const float2*)(prow0 + ks * 8 + 2 * t4);
            float2 a13 = *(const float2*)(prow1 + ks * 8 + 2 * t4);
            uint32_t af[4] = {__float_as_uint(a02.x), __float_as_uint(a13.x),
                              __float_as_uint(a02.y), __float_as_uint(a13.y)};
#pragma unroll
            for (int nt = 0; nt < 8; ++nt) {
                float2 bb = *(const float2*)&Vt[(nt * 8 + g) * AST + ks * 8 + 2 * t4];
                uint32_t bf[2] = {__float_as_uint(bb.x), __float_as_uint(bb.y)};
                mma16n8k8(oacc[nt], af, bf);
            }
        }
        __syncthreads();   // protect Ks/Vt/Ps before next staging
    }

    // ---- epilogue ----
    float inv0 = 1.f / l0, inv1 = 1.f / l1;
    float* o0 = g_att + headoff + (size_t)(qbase + w * 16 + g) * HID;
    float* o1 = o0 + (size_t)8 * HID;
#pragma unroll
    for (int nt = 0; nt < 8; ++nt) {
        int c = nt * 8 + 2 * t4;
        *(float2*)(o0 + c) = make_float2(oacc[nt][0] * inv0, oacc[nt][1] * inv0);
        *(float2*)(o1 + c) = make_float2(oacc[nt][2] * inv1, oacc[nt][3] * inv1);
    }
}

// ----------------------------------------------------------------------------
extern "C" void kernel_launch(void* const* d_in, const int* in_sizes, int n_in,
                              void* d_out, int out_size) {
    const float* x  = (const float*)d_in[0];
    const float* Wq = (const float*)d_in[1];
    const float* Wk = (const float*)d_in[2];
    const float* Wv = (const float*)d_in[3];
    const float* Wo = (const float*)d_in[4];
    float* out = (float*)d_out;

    cudaFuncSetAttribute(attn_kernel,
                         cudaFuncAttributeMaxDynamicSharedMemorySize, ATTN_SMEM);

    dim3 gqkv(HID / BN, MROWS / BM, 3);     // 8 x 32 x 3
    qkv_kernel<<<gqkv, 256>>>(x, Wq, Wk, Wv);

    dim3 gattn(SEQ / 128, NB * NHEAD);      // 16 x 32
    attn_kernel<<<gattn, 256, ATTN_SMEM>>>();

    dim3 gproj(HID / BN, MROWS / BM);       // 8 x 32
    proj_kernel<<<gproj, 256>>>(Wo, out);
}

// round 13
// speedup vs baseline: 3.4229x; 1.2664x over previous
#include <cuda_runtime.h>
#include <cuda_bf16.h>
#include <cstdint>

#define HID 1024
#define NHEAD 16
#define HD 64
#define NB 2
#define SEQ 2048
#define MROWS (NB * SEQ)   // 4096

// Scratch (allocation-free rule: __device__ globals)
__device__ float g_q[MROWS * HID];
__device__ float g_k[MROWS * HID];
__device__ float g_v[MROWS * HID];
__device__ float g_att[MROWS * HID];

__device__ __forceinline__ uint32_t f2tf32(float x) {
    uint32_t r;
    asm("cvt.rna.tf32.f32 %0, %1;" : "=r"(r) : "f"(x));
    return r;
}

__device__ __forceinline__ void mma16n8k8(float* d, const uint32_t* a, const uint32_t* b) {
    asm volatile(
        "mma.sync.aligned.m16n8k8.row.col.f32.tf32.tf32.f32 "
        "{%0,%1,%2,%3}, {%4,%5,%6,%7}, {%8,%9}, {%0,%1,%2,%3};\n"
        : "+f"(d[0]), "+f"(d[1]), "+f"(d[2]), "+f"(d[3])
        : "r"(a[0]), "r"(a[1]), "r"(a[2]), "r"(a[3]),
          "r"(b[0]), "r"(b[1]));
}

// ----------------------------------------------------------------------------
// tf32 tensor-core GEMM (unchanged from R10 — protects that win)
// ----------------------------------------------------------------------------
#define BM 128
#define BN 128
#define BKT 16
#define ST 24

__device__ __forceinline__ int eswz(int m) {
    return (((m & 1) << 1) | ((m >> 2) & 1)) << 1;
}

__device__ __forceinline__ void gemm_nt_tc(const float* __restrict__ A,
                                           const float* __restrict__ W,
                                           float* __restrict__ Y,
                                           int K, int N) {
    __shared__ uint32_t As[BM][ST];
    __shared__ uint32_t Ws[BN][ST];

    const int tid  = threadIdx.x;
    const int lane = tid & 31;
    const int warp = tid >> 5;
    const int wm   = warp & 1;
    const int wn   = warp >> 1;
    const int g    = lane >> 2;
    const int t4   = lane & 3;

    const int bm = blockIdx.y * BM;
    const int bn = blockIdx.x * BN;

    const int lr   = tid >> 1;
    const int half = tid & 1;
    const int lc   = half * 8;

    const float* Aptr = A + (size_t)(bm + lr) * K + lc;
    const float* Wptr = W + (size_t)(bn + lr) * K + lc;

    const int se = eswz(lr);
    uint32_t* arow = &As[lr][half * 8];
    uint32_t* wrow = &Ws[lr][half * 8];

    float acc[4][4][4];
#pragma unroll
    for (int i = 0; i < 4; ++i)
#pragma unroll
        for (int j = 0; j < 4; ++j)
#pragma unroll
            for (int q = 0; q < 4; ++q) acc[i][j][q] = 0.f;

    float4 a0 = *(const float4*)(Aptr);
    float4 a1 = *(const float4*)(Aptr + 4);
    float4 w0 = *(const float4*)(Wptr);
    float4 w1 = *(const float4*)(Wptr + 4);

    for (int k0 = 0; k0 < K; k0 += BKT) {
        *(uint2*)&arow[0 ^ se] = make_uint2(f2tf32(a0.x), f2tf32(a1.x));
        *(uint2*)&arow[2 ^ se] = make_uint2(f2tf32(a0.y), f2tf32(a1.y));
        *(uint2*)&arow[4 ^ se] = make_uint2(f2tf32(a0.z), f2tf32(a1.z));
        *(uint2*)&arow[6 ^ se] = make_uint2(f2tf32(a0.w), f2tf32(a1.w));
        *(uint2*)&wrow[0 ^ se] = make_uint2(f2tf32(w0.x), f2tf32(w1.x));
        *(uint2*)&wrow[2 ^ se] = make_uint2(f2tf32(w0.y), f2tf32(w1.y));
        *(uint2*)&wrow[4 ^ se] = make_uint2(f2tf32(w0.z), f2tf32(w1.z));
        *(uint2*)&wrow[6 ^ se] = make_uint2(f2tf32(w0.w), f2tf32(w1.w));
        __syncthreads();

        if (k0 + BKT < K) {
            a0 = *(const float4*)(Aptr + k0 + BKT);
            a1 = *(const float4*)(Aptr + k0 + BKT + 4);
            w0 = *(const float4*)(Wptr + k0 + BKT);
            w1 = *(const float4*)(Wptr + k0 + BKT + 4);
        }

#pragma unroll
        for (int ksb = 0; ksb < 2; ++ksb) {
            uint32_t af[4][4];
            uint32_t bf[4][2];
#pragma unroll
            for (int mt = 0; mt < 4; ++mt) {
                int r0 = wm * 64 + mt * 16 + g;
                int em = eswz(r0);
                uint2 p = *(const uint2*)&As[r0][ksb * 8 + (2 * t4 ^ em)];
                uint2 q = *(const uint2*)&As[r0 + 8][ksb * 8 + (2 * t4 ^ em)];
                af[mt][0] = p.x; af[mt][1] = q.x;
                af[mt][2] = p.y; af[mt][3] = q.y;
            }
#pragma unroll
            for (int nt = 0; nt < 4; ++nt) {
                int n0 = wn * 32 + nt * 8 + g;
                int en = eswz(n0);
                uint2 r = *(const uint2*)&Ws[n0][ksb * 8 + (2 * t4 ^ en)];
                bf[nt][0] = r.x; bf[nt][1] = r.y;
            }
#pragma unroll
            for (int mt = 0; mt < 4; ++mt)
#pragma unroll
                for (int nt = 0; nt < 4; ++nt)
                    mma16n8k8(acc[mt][nt], af[mt], bf[nt]);
        }
        __syncthreads();
    }

#pragma unroll
    for (int mt = 0; mt < 4; ++mt) {
        int r0 = bm + wm * 64 + mt * 16 + g;
#pragma unroll
        for (int nt = 0; nt < 4; ++nt) {
            int c = bn + wn * 32 + nt * 8 + 2 * t4;
            *(float2*)(Y + (size_t)r0 * N + c) =
                make_float2(acc[mt][nt][0], acc[mt][nt][1]);
            *(float2*)(Y + (size_t)(r0 + 8) * N + c) =
                make_float2(acc[mt][nt][2], acc[mt][nt][3]);
        }
    }
}

__global__ void __launch_bounds__(256, 2)
qkv_kernel(const float* __restrict__ x,
           const float* __restrict__ Wq,
           const float* __restrict__ Wk,
           const float* __restrict__ Wv) {
    const float* W;
    float* Y;
    if (blockIdx.z == 0)      { W = Wq; Y = g_q; }
    else if (blockIdx.z == 1) { W = Wk; Y = g_k; }
    else                      { W = Wv; Y = g_v; }
    gemm_nt_tc(x, W, Y, HID, HID);
}

__global__ void __launch_bounds__(256, 2)
proj_kernel(const float* __restrict__ Wo, float* __restrict__ out) {
    gemm_nt_tc(g_att, Wo, out, HID, HID);
}

// ----------------------------------------------------------------------------
// Tensor-core causal flash attention v2.
// Slot remap phys = 2*(slot&3) + (slot>>2): natural-order smem tiles,
// LDS.64 fragment pairs, conflict-free STS.128 staging, P in registers
// (no Ps buffer). Q/K stride 72, V stride 68. smem 36864 B -> 2 CTAs/SM.
// ----------------------------------------------------------------------------
#define QST 72
#define KST 72
#define VST 68
#define ATTN_SMEM (128 * QST * 4)   // 36864 B; K(18432)+V(17408) overlay inside

__global__ void __launch_bounds__(256, 2) attn_kernel() {
    extern __shared__ float sm[];
    float* Qs = sm;                 // [128][QST] (staging phase only)
    float* Ks = sm;                 // [64][KST]  (loop phase)
    float* Vs = sm + 64 * KST;      // [64][VST]

    const int tid  = threadIdx.x;
    const int lane = tid & 31;
    const int w    = tid >> 5;
    const int g    = lane >> 2;
    const int t4   = lane & 3;

    const int qt = (int)gridDim.x - 1 - (int)blockIdx.x;  // heavy tiles first
    const int bh = blockIdx.y;
    const int b  = bh >> 4;
    const int h  = bh & 15;
    const size_t headoff = (size_t)b * SEQ * HID + (size_t)h * HD;
    const int qbase = qt * 128;

    const int srow = tid >> 4;      // 0..15 staging row base
    const int sch  = tid & 15;      // 16B chunk index

    // ---- stage Q (scaled by 1/8, tf32) ----
#pragma unroll
    for (int s = 0; s < 8; ++s) {
        int r = srow + 16 * s;
        float4 v = *(const float4*)(g_q + headoff + (size_t)(qbase + r) * HID + sch * 4);
        uint4 u = make_uint4(f2tf32(v.x * 0.125f), f2tf32(v.y * 0.125f),
                             f2tf32(v.z * 0.125f), f2tf32(v.w * 0.125f));
        *(uint4*)&Qs[r * QST + sch * 4] = u;
    }
    __syncthreads();

    // ---- preload Q fragments: a-slots (t4, t4+4) <- phys (2t4, 2t4+1) ----
    uint32_t qf[8][4];
#pragma unroll
    for (int oct = 0; oct < 8; ++oct) {
        uint2 p0 = *(const uint2*)&Qs[(w * 16 + g) * QST + oct * 8 + 2 * t4];
        uint2 p1 = *(const uint2*)&Qs[(w * 16 + g + 8) * QST + oct * 8 + 2 * t4];
        qf[oct][0] = p0.x; qf[oct][1] = p1.x;
        qf[oct][2] = p0.y; qf[oct][3] = p1.y;
    }
    __syncthreads();   // Q consumed; smem becomes K/V

    float m0 = -1e30f, m1 = -1e30f, l0 = 0.f, l1 = 0.f;
    float oacc[8][4];
#pragma unroll
    for (int nt = 0; nt < 8; ++nt)
#pragma unroll
        for (int q = 0; q < 4; ++q) oacc[nt][q] = 0.f;

    const int row0 = qbase + w * 16 + g;
    const int row1 = row0 + 8;

    const int nkt = 2 * qt + 2;
    for (int kt = 0; kt < nkt; ++kt) {
        // ---- stage K and V tiles (natural layout, conflict-free STS.128) ----
#pragma unroll
        for (int s = 0; s < 4; ++s) {
            int r = srow + 16 * s;
            size_t goff = headoff + (size_t)(kt * 64 + r) * HID + sch * 4;
            float4 kv4 = *(const float4*)(g_k + goff);
            *(uint4*)&Ks[r * KST + sch * 4] =
                make_uint4(f2tf32(kv4.x), f2tf32(kv4.y), f2tf32(kv4.z), f2tf32(kv4.w));
            float4 vv4 = *(const float4*)(g_v + goff);
            *(uint4*)&Vs[r * VST + sch * 4] =
                make_uint4(f2tf32(vv4.x), f2tf32(vv4.y), f2tf32(vv4.z), f2tf32(vv4.w));
        }
        __syncthreads();

        // ---- S = Q K^T  (contraction over phys d via slot remap) ----
        float sacc[8][4];
#pragma unroll
        for (int nt = 0; nt < 8; ++nt)
#pragma unroll
            for (int q = 0; q < 4; ++q) sacc[nt][q] = 0.f;

#pragma unroll
        for (int nt = 0; nt < 8; ++nt) {
            const float* krow = &Ks[(nt * 8 + g) * KST + 2 * t4];
#pragma unroll
            for (int oct = 0; oct < 8; ++oct) {
                uint2 bb = *(const uint2*)(krow + oct * 8);
                uint32_t bf[2] = {bb.x, bb.y};
                mma16n8k8(sacc[nt], qf[oct], bf);
            }
        }

        // ---- causal mask (only last two k-tiles can clip) ----
        if (kt >= 2 * qt) {
            int colb = kt * 64 + 2 * t4;
#pragma unroll
            for (int nt = 0; nt < 8; ++nt) {
                int c = colb + nt * 8;
                if (c     > row0) sacc[nt][0] = -1e30f;
                if (c + 1 > row0) sacc[nt][1] = -1e30f;
                if (c     > row1) sacc[nt][2] = -1e30f;
                if (c + 1 > row1) sacc[nt][3] = -1e30f;
            }
        }

        // ---- online softmax (quad shuffles; rows live in one quad) ----
        float mx0 = -1e30f, mx1 = -1e30f;
#pragma unroll
        for (int nt = 0; nt < 8; ++nt) {
            mx0 = fmaxf(mx0, fmaxf(sacc[nt][0], sacc[nt][1]));
            mx1 = fmaxf(mx1, fmaxf(sacc[nt][2], sacc[nt][3]));
        }
        mx0 = fmaxf(mx0, __shfl_xor_sync(0xffffffffu, mx0, 1));
        mx0 = fmaxf(mx0, __shfl_xor_sync(0xffffffffu, mx0, 2));
        mx1 = fmaxf(mx1, __shfl_xor_sync(0xffffffffu, mx1, 1));
        mx1 = fmaxf(mx1, __shfl_xor_sync(0xffffffffu, mx1, 2));

        float mn0 = fmaxf(m0, mx0), mn1 = fmaxf(m1, mx1);
        float al0 = __expf(m0 - mn0), al1 = __expf(m1 - mn1);
        m0 = mn0; m1 = mn1;

        float rs0 = 0.f, rs1 = 0.f;
#pragma unroll
        for (int nt = 0; nt < 8; ++nt) {
            sacc[nt][0] = __expf(sacc[nt][0] - m0);
            sacc[nt][1] = __expf(sacc[nt][1] - m0);
            sacc[nt][2] = __expf(sacc[nt][2] - m1);
            sacc[nt][3] = __expf(sacc[nt][3] - m1);
            rs0 += sacc[nt][0] + sacc[nt][1];
            rs1 += sacc[nt][2] + sacc[nt][3];
            oacc[nt][0] *= al0; oacc[nt][1] *= al0;
            oacc[nt][2] *= al1; oacc[nt][3] *= al1;
        }
        rs0 += __shfl_xor_sync(0xffffffffu, rs0, 1);
        rs0 += __shfl_xor_sync(0xffffffffu, rs0, 2);
        rs1 += __shfl_xor_sync(0xffffffffu, rs1, 1);
        rs1 += __shfl_xor_sync(0xffffffffu, rs1, 2);
        l0 = l0 * al0 + rs0;
        l1 = l1 * al1 + rs1;

        // ---- O += P V : P fragments are the softmax registers in place ----
#pragma unroll
        for (int oct = 0; oct < 8; ++oct) {
            uint32_t af[4] = {f2tf32(sacc[oct][0]), f2tf32(sacc[oct][2]),
                              f2tf32(sacc[oct][1]), f2tf32(sacc[oct][3])};
            const float* vrow0 = &Vs[(oct * 8 + 2 * t4) * VST + g];
#pragma unroll
            for (int nt = 0; nt < 8; ++nt) {
                uint32_t bf[2] = {__float_as_uint(vrow0[nt * 8]),
                                  __float_as_uint(vrow0[VST + nt * 8])};
                mma16n8k8(oacc[nt], af, bf);
            }
        }
        __syncthreads();   // protect Ks/Vs before next staging
    }

    // ---- epilogue ----
    float inv0 = 1.f / l0, inv1 = 1.f / l1;
    float* o0 = g_att + headoff + (size_t)(qbase + w * 16 + g) * HID;
    float* o1 = o0 + (size_t)8 * HID;
#pragma unroll
    for (int nt = 0; nt < 8; ++nt) {
        int c = nt * 8 + 2 * t4;
        *(float2*)(o0 + c) = make_float2(oacc[nt][0] * inv0, oacc[nt][1] * inv0);
        *(float2*)(o1 + c) = make_float2(oacc[nt][2] * inv1, oacc[nt][3] * inv1);
    }
}

// ----------------------------------------------------------------------------
extern "C" void kernel_launch(void* const* d_in, const int* in_sizes, int n_in,
                              void* d_out, int out_size) {
    const float* x  = (const float*)d_in[0];
    const float* Wq = (const float*)d_in[1];
    const float* Wk = (const float*)d_in[2];
    const float* Wv = (const float*)d_in[3];
    const float* Wo = (const float*)d_in[4];
    float* out = (float*)d_out;

    cudaFuncSetAttribute(attn_kernel,
                         cudaFuncAttributeMaxDynamicSharedMemorySize, ATTN_SMEM);

    dim3 gqkv(HID / BN, MROWS / BM, 3);     // 8 x 32 x 3
    qkv_kernel<<<gqkv, 256>>>(x, Wq, Wk, Wv);

    dim3 gattn(SEQ / 128, NB * NHEAD);      // 16 x 32
    attn_kernel<<<gattn, 256, ATTN_SMEM>>>();

    dim3 gproj(HID / BN, MROWS / BM);       // 8 x 32
    proj_kernel<<<gproj, 256>>>(Wo, out);
}

// round 14
// speedup vs baseline: 3.7238x; 1.0879x over previous
#include <cuda_runtime.h>
#include <cuda_bf16.h>
#include <cstdint>

#define HID 1024
#define NHEAD 16
#define HD 64
#define NB 2
#define SEQ 2048
#define MROWS (NB * SEQ)   // 4096

// Scratch (allocation-free rule: __device__ globals)
__device__ float g_q[MROWS * HID];
__device__ float g_k[MROWS * HID];
__device__ float g_v[MROWS * HID];
__device__ float g_att[MROWS * HID];

__device__ __forceinline__ uint32_t f2tf32(float x) {
    uint32_t r;
    asm("cvt.rna.tf32.f32 %0, %1;" : "=r"(r) : "f"(x));
    return r;
}

__device__ __forceinline__ void mma16n8k8(float* d, const uint32_t* a, const uint32_t* b) {
    asm volatile(
        "mma.sync.aligned.m16n8k8.row.col.f32.tf32.tf32.f32 "
        "{%0,%1,%2,%3}, {%4,%5,%6,%7}, {%8,%9}, {%0,%1,%2,%3};\n"
        : "+f"(d[0]), "+f"(d[1]), "+f"(d[2]), "+f"(d[3])
        : "r"(a[0]), "r"(a[1]), "r"(a[2]), "r"(a[3]),
          "r"(b[0]), "r"(b[1]));
}

__device__ __forceinline__ void cp_async16(uint32_t smem_dst, const void* gsrc) {
    asm volatile("cp.async.cg.shared.global [%0], [%1], 16;\n"
                 :: "r"(smem_dst), "l"(gsrc));
}
__device__ __forceinline__ void cp_commit() {
    asm volatile("cp.async.commit_group;\n");
}
template <int N>
__device__ __forceinline__ void cp_wait() {
    asm volatile("cp.async.wait_group %0;\n" :: "n"(N));
}

// ----------------------------------------------------------------------------
// tf32 tensor-core GEMM v3:  Y[M,N] = A[M,K] @ W[N,K]^T
// cp.async double-buffered pipeline; smem holds raw f32 rows [r][16] with
// 16B-chunk XOR swizzle (chunk ^= r&3); tf32 conversion at fragment load.
// MMA k-slot remap phys = 2*(slot&3) + (slot>>2) (same for A and B) makes
// fragment pairs (slot t4, t4+4) one LDS.64. All phases bank-conflict-free.
// ----------------------------------------------------------------------------
#define BM 128
#define BN 128
#define BKG 16

__device__ __forceinline__ void gemm_nt_tc(const float* __restrict__ A,
                                           const float* __restrict__ W,
                                           float* __restrict__ Y,
                                           int K, int N) {
    __shared__ float As[2][BM][16];
    __shared__ float Ws[2][BN][16];

    const int tid  = threadIdx.x;
    const int lane = tid & 31;
    const int warp = tid >> 5;
    const int wm   = warp & 1;          // 0..1 -> 64-row slice
    const int wn   = warp >> 1;         // 0..3 -> 32-col slice
    const int g    = lane >> 2;         // 0..7
    const int t4   = lane & 3;          // 0..3

    const int bm = blockIdx.y * BM;
    const int bn = blockIdx.x * BN;

    // Loader: 4 lanes per row, lane covers one 16B k-chunk.
    const int r1 = tid >> 2;            // 0..63
    const int r2 = r1 + 64;
    const int cc = tid & 3;
    const int cw = (cc ^ (r1 & 3)) * 4; // swizzled word offset (r2&3 == r1&3)

    const float* Ap1 = A + (size_t)(bm + r1) * K + cc * 4;
    const float* Ap2 = A + (size_t)(bm + r2) * K + cc * 4;
    const float* Wp1 = W + (size_t)(bn + r1) * K + cc * 4;
    const float* Wp2 = W + (size_t)(bn + r2) * K + cc * 4;

    const uint32_t sA1 = (uint32_t)__cvta_generic_to_shared(&As[0][r1][cw]);
    const uint32_t sA2 = (uint32_t)__cvta_generic_to_shared(&As[0][r2][cw]);
    const uint32_t sW1 = (uint32_t)__cvta_generic_to_shared(&Ws[0][r1][cw]);
    const uint32_t sW2 = (uint32_t)__cvta_generic_to_shared(&Ws[0][r2][cw]);
    const uint32_t stgoff = BM * 16 * 4;   // 8192 B per stage

    float acc[4][4][4];
#pragma unroll
    for (int i = 0; i < 4; ++i)
#pragma unroll
        for (int j = 0; j < 4; ++j)
#pragma unroll
            for (int q = 0; q < 4; ++q) acc[i][j][q] = 0.f;

    const int niter = K / BKG;          // 64

    // prologue: stage 0
    cp_async16(sA1, Ap1);
    cp_async16(sA2, Ap2);
    cp_async16(sW1, Wp1);
    cp_async16(sW2, Wp2);
    cp_commit();

    for (int i = 0; i < niter; ++i) {
        const int s = i & 1;
        if (i + 1 < niter) {
            const uint32_t so = (uint32_t)((i + 1) & 1) * stgoff;
            const int go = (i + 1) * BKG;
            cp_async16(sA1 + so, Ap1 + go);
            cp_async16(sA2 + so, Ap2 + go);
            cp_async16(sW1 + so, Wp1 + go);
            cp_async16(sW2 + so, Wp2 + go);
            cp_commit();
            cp_wait<1>();
        } else {
            cp_wait<0>();
        }
        __syncthreads();

#pragma unroll
        for (int ksb = 0; ksb < 2; ++ksb) {
            // swizzled word offset for this (ksb, t4), same for all rows used
            // (all fragment rows satisfy row & 3 == g & 3)
            const int chunk = ksb * 2 + (t4 >> 1);
            const int w0 = ((chunk ^ (g & 3)) << 2) + ((2 * t4) & 3);

            uint32_t af[4][4];
            uint32_t bf[4][2];
#pragma unroll
            for (int mt = 0; mt < 4; ++mt) {
                int r0 = wm * 64 + mt * 16 + g;
                float2 p = *(const float2*)&As[s][r0][w0];
                float2 q = *(const float2*)&As[s][r0 + 8][w0];
                af[mt][0] = f2tf32(p.x); af[mt][1] = f2tf32(q.x);
                af[mt][2] = f2tf32(p.y); af[mt][3] = f2tf32(q.y);
            }
#pragma unroll
            for (int nt = 0; nt < 4; ++nt) {
                int n0 = wn * 32 + nt * 8 + g;
                float2 r = *(const float2*)&Ws[s][n0][w0];
                bf[nt][0] = f2tf32(r.x); bf[nt][1] = f2tf32(r.y);
            }
#pragma unroll
            for (int mt = 0; mt < 4; ++mt)
#pragma unroll
                for (int nt = 0; nt < 4; ++nt)
                    mma16n8k8(acc[mt][nt], af[mt], bf[nt]);
        }
        __syncthreads();
    }

#pragma unroll
    for (int mt = 0; mt < 4; ++mt) {
        int r0 = bm + wm * 64 + mt * 16 + g;
#pragma unroll
        for (int nt = 0; nt < 4; ++nt) {
            int c = bn + wn * 32 + nt * 8 + 2 * t4;
            *(float2*)(Y + (size_t)r0 * N + c) =
                make_float2(acc[mt][nt][0], acc[mt][nt][1]);
            *(float2*)(Y + (size_t)(r0 + 8) * N + c) =
                make_float2(acc[mt][nt][2], acc[mt][nt][3]);
        }
    }
}

__global__ void __launch_bounds__(256, 2)
qkv_kernel(const float* __restrict__ x,
           const float* __restrict__ Wq,
           const float* __restrict__ Wk,
           const float* __restrict__ Wv) {
    const float* W;
    float* Y;
    if (blockIdx.z == 0)      { W = Wq; Y = g_q; }
    else if (blockIdx.z == 1) { W = Wk; Y = g_k; }
    else                      { W = Wv; Y = g_v; }
    gemm_nt_tc(x, W, Y, HID, HID);
}

__global__ void __launch_bounds__(256, 2)
proj_kernel(const float* __restrict__ Wo, float* __restrict__ out) {
    gemm_nt_tc(g_att, Wo, out, HID, HID);
}

// ----------------------------------------------------------------------------
// Tensor-core causal flash attention v2 (unchanged from R13 — protects win).
// ----------------------------------------------------------------------------
#define QST 72
#define KST 72
#define VST 68
#define ATTN_SMEM (128 * QST * 4)   // 36864 B

__global__ void __launch_bounds__(256, 2) attn_kernel() {
    extern __shared__ float sm[];
    float* Qs = sm;                 // [128][QST] (staging phase only)
    float* Ks = sm;                 // [64][KST]  (loop phase)
    float* Vs = sm + 64 * KST;      // [64][VST]

    const int tid  = threadIdx.x;
    const int lane = tid & 31;
    const int w    = tid >> 5;
    const int g    = lane >> 2;
    const int t4   = lane & 3;

    const int qt = (int)gridDim.x - 1 - (int)blockIdx.x;  // heavy tiles first
    const int bh = blockIdx.y;
    const int b  = bh >> 4;
    const int h  = bh & 15;
    const size_t headoff = (size_t)b * SEQ * HID + (size_t)h * HD;
    const int qbase = qt * 128;

    const int srow = tid >> 4;
    const int sch  = tid & 15;

    // ---- stage Q (scaled by 1/8, tf32) ----
#pragma unroll
    for (int s = 0; s < 8; ++s) {
        int r = srow + 16 * s;
        float4 v = *(const float4*)(g_q + headoff + (size_t)(qbase + r) * HID + sch * 4);
        uint4 u = make_uint4(f2tf32(v.x * 0.125f), f2tf32(v.y * 0.125f),
                             f2tf32(v.z * 0.125f), f2tf32(v.w * 0.125f));
        *(uint4*)&Qs[r * QST + sch * 4] = u;
    }
    __syncthreads();

    uint32_t qf[8][4];
#pragma unroll
    for (int oct = 0; oct < 8; ++oct) {
        uint2 p0 = *(const uint2*)&Qs[(w * 16 + g) * QST + oct * 8 + 2 * t4];
        uint2 p1 = *(const uint2*)&Qs[(w * 16 + g + 8) * QST + oct * 8 + 2 * t4];
        qf[oct][0] = p0.x; qf[oct][1] = p1.x;
        qf[oct][2] = p0.y; qf[oct][3] = p1.y;
    }
    __syncthreads();

    float m0 = -1e30f, m1 = -1e30f, l0 = 0.f, l1 = 0.f;
    float oacc[8][4];
#pragma unroll
    for (int nt = 0; nt < 8; ++nt)
#pragma unroll
        for (int q = 0; q < 4; ++q) oacc[nt][q] = 0.f;

    const int row0 = qbase + w * 16 + g;
    const int row1 = row0 + 8;

    const int nkt = 2 * qt + 2;
    for (int kt = 0; kt < nkt; ++kt) {
#pragma unroll
        for (int s = 0; s < 4; ++s) {
            int r = srow + 16 * s;
            size_t goff = headoff + (size_t)(kt * 64 + r) * HID + sch * 4;
            float4 kv4 = *(const float4*)(g_k + goff);
            *(uint4*)&Ks[r * KST + sch * 4] =
                make_uint4(f2tf32(kv4.x), f2tf32(kv4.y), f2tf32(kv4.z), f2tf32(kv4.w));
            float4 vv4 = *(const float4*)(g_v + goff);
            *(uint4*)&Vs[r * VST + sch * 4] =
                make_uint4(f2tf32(vv4.x), f2tf32(vv4.y), f2tf32(vv4.z), f2tf32(vv4.w));
        }
        __syncthreads();

        float sacc[8][4];
#pragma unroll
        for (int nt = 0; nt < 8; ++nt)
#pragma unroll
            for (int q = 0; q < 4; ++q) sacc[nt][q] = 0.f;

#pragma unroll
        for (int nt = 0; nt < 8; ++nt) {
            const float* krow = &Ks[(nt * 8 + g) * KST + 2 * t4];
#pragma unroll
            for (int oct = 0; oct < 8; ++oct) {
                uint2 bb = *(const uint2*)(krow + oct * 8);
                uint32_t bf[2] = {bb.x, bb.y};
                mma16n8k8(sacc[nt], qf[oct], bf);
            }
        }

        if (kt >= 2 * qt) {
            int colb = kt * 64 + 2 * t4;
#pragma unroll
            for (int nt = 0; nt < 8; ++nt) {
                int c = colb + nt * 8;
                if (c     > row0) sacc[nt][0] = -1e30f;
                if (c + 1 > row0) sacc[nt][1] = -1e30f;
                if (c     > row1) sacc[nt][2] = -1e30f;
                if (c + 1 > row1) sacc[nt][3] = -1e30f;
            }
        }

        float mx0 = -1e30f, mx1 = -1e30f;
#pragma unroll
        for (int nt = 0; nt < 8; ++nt) {
            mx0 = fmaxf(mx0, fmaxf(sacc[nt][0], sacc[nt][1]));
            mx1 = fmaxf(mx1, fmaxf(sacc[nt][2], sacc[nt][3]));
        }
        mx0 = fmaxf(mx0, __shfl_xor_sync(0xffffffffu, mx0, 1));
        mx0 = fmaxf(mx0, __shfl_xor_sync(0xffffffffu, mx0, 2));
        mx1 = fmaxf(mx1, __shfl_xor_sync(0xffffffffu, mx1, 1));
        mx1 = fmaxf(mx1, __shfl_xor_sync(0xffffffffu, mx1, 2));

        float mn0 = fmaxf(m0, mx0), mn1 = fmaxf(m1, mx1);
        float al0 = __expf(m0 - mn0), al1 = __expf(m1 - mn1);
        m0 = mn0; m1 = mn1;

        float rs0 = 0.f, rs1 = 0.f;
#pragma unroll
        for (int nt = 0; nt < 8; ++nt) {
            sacc[nt][0] = __expf(sacc[nt][0] - m0);
            sacc[nt][1] = __expf(sacc[nt][1] - m0);
            sacc[nt][2] = __expf(sacc[nt][2] - m1);
            sacc[nt][3] = __expf(sacc[nt][3] - m1);
            rs0 += sacc[nt][0] + sacc[nt][1];
            rs1 += sacc[nt][2] + sacc[nt][3];
            oacc[nt][0] *= al0; oacc[nt][1] *= al0;
            oacc[nt][2] *= al1; oacc[nt][3] *= al1;
        }
        rs0 += __shfl_xor_sync(0xffffffffu, rs0, 1);
        rs0 += __shfl_xor_sync(0xffffffffu, rs0, 2);
        rs1 += __shfl_xor_sync(0xffffffffu, rs1, 1);
        rs1 += __shfl_xor_sync(0xffffffffu, rs1, 2);
        l0 = l0 * al0 + rs0;
        l1 = l1 * al1 + rs1;

#pragma unroll
        for (int oct = 0; oct < 8; ++oct) {
            uint32_t af[4] = {f2tf32(sacc[oct][0]), f2tf32(sacc[oct][2]),
                              f2tf32(sacc[oct][1]), f2tf32(sacc[oct][3])};
            const float* vrow0 = &Vs[(oct * 8 + 2 * t4) * VST + g];
#pragma unroll
            for (int nt = 0; nt < 8; ++nt) {
                uint32_t bf[2] = {__float_as_uint(vrow0[nt * 8]),
                                  __float_as_uint(vrow0[VST + nt * 8])};
                mma16n8k8(oacc[nt], af, bf);
            }
        }
        __syncthreads();
    }

    float inv0 = 1.f / l0, inv1 = 1.f / l1;
    float* o0 = g_att + headoff + (size_t)(qbase + w * 16 + g) * HID;
    float* o1 = o0 + (size_t)8 * HID;
#pragma unroll
    for (int nt = 0; nt < 8; ++nt) {
        int c = nt * 8 + 2 * t4;
        *(float2*)(o0 + c) = make_float2(oacc[nt][0] * inv0, oacc[nt][1] * inv0);
        *(float2*)(o1 + c) = make_float2(oacc[nt][2] * inv1, oacc[nt][3] * inv1);
    }
}

// ----------------------------------------------------------------------------
extern "C" void kernel_launch(void* const* d_in, const int* in_sizes, int n_in,
                              void* d_out, int out_size) {
    const float* x  = (const float*)d_in[0];
    const float* Wq = (const float*)d_in[1];
    const float* Wk = (const float*)d_in[2];
    const float* Wv = (const float*)d_in[3];
    const float* Wo = (const float*)d_in[4];
    float* out = (float*)d_out;

    cudaFuncSetAttribute(attn_kernel,
                         cudaFuncAttributeMaxDynamicSharedMemorySize, ATTN_SMEM);

    dim3 gqkv(HID / BN, MROWS / BM, 3);     // 8 x 32 x 3
    qkv_kernel<<<gqkv, 256>>>(x, Wq, Wk, Wv);

    dim3 gattn(SEQ / 128, NB * NHEAD);      // 16 x 32
    attn_kernel<<<gattn, 256, ATTN_SMEM>>>();

    dim3 gproj(HID / BN, MROWS / BM);       // 8 x 32
    proj_kernel<<<gproj, 256>>>(Wo, out);
}

// round 15
// speedup vs baseline: 4.0405x; 1.0851x over previous
#include <cuda_runtime.h>
#include <cuda_bf16.h>
#include <cstdint>

#define HID 1024
#define NHEAD 16
#define HD 64
#define NB 2
#define SEQ 2048
#define MROWS (NB * SEQ)   // 4096

// Scratch (allocation-free rule: __device__ globals)
__device__ float g_q[MROWS * HID];
__device__ float g_k[MROWS * HID];
__device__ float g_v[MROWS * HID];
__device__ float g_att[MROWS * HID];
// tf32-pre-rounded copies of inputs
__device__ float g_xr[MROWS * HID];
__device__ float g_wq[HID * HID];
__device__ float g_wk[HID * HID];
__device__ float g_wv[HID * HID];
__device__ float g_wo[HID * HID];

__device__ __forceinline__ uint32_t f2tf32(float x) {
    uint32_t r;
    asm("cvt.rna.tf32.f32 %0, %1;" : "=r"(r) : "f"(x));
    return r;
}

__device__ __forceinline__ void mma16n8k8(float* d, const uint32_t* a, const uint32_t* b) {
    asm volatile(
        "mma.sync.aligned.m16n8k8.row.col.f32.tf32.tf32.f32 "
        "{%0,%1,%2,%3}, {%4,%5,%6,%7}, {%8,%9}, {%0,%1,%2,%3};\n"
        : "+f"(d[0]), "+f"(d[1]), "+f"(d[2]), "+f"(d[3])
        : "r"(a[0]), "r"(a[1]), "r"(a[2]), "r"(a[3]),
          "r"(b[0]), "r"(b[1]));
}

__device__ __forceinline__ void cp_async16(uint32_t smem_dst, const void* gsrc) {
    asm volatile("cp.async.cg.shared.global [%0], [%1], 16;\n"
                 :: "r"(smem_dst), "l"(gsrc));
}
__device__ __forceinline__ void cp_commit() {
    asm volatile("cp.async.commit_group;\n");
}
template <int N>
__device__ __forceinline__ void cp_wait() {
    asm volatile("cp.async.wait_group %0;\n" :: "n"(N));
}

// ----------------------------------------------------------------------------
// Pre-round pass: x + 4 weight matrices -> tf32-rounded fp32 globals.
// float4 per thread. x: 1048576 float4, each W: 262144 float4.
// ----------------------------------------------------------------------------
#define XF4 (MROWS * HID / 4)    // 1048576
#define WF4 (HID * HID / 4)      // 262144

__global__ void __launch_bounds__(256)
round_kernel(const float* __restrict__ x,
             const float* __restrict__ wq, const float* __restrict__ wk,
             const float* __restrict__ wv, const float* __restrict__ wo) {
    int i = blockIdx.x * blockDim.x + threadIdx.x;   // float4 idx
    const float* src;
    float* dst;
    int j;
    if (i < XF4)                    { src = x;  dst = g_xr; j = i; }
    else if (i < XF4 + WF4)         { src = wq; dst = g_wq; j = i - XF4; }
    else if (i < XF4 + 2 * WF4)     { src = wk; dst = g_wk; j = i - XF4 - WF4; }
    else if (i < XF4 + 3 * WF4)     { src = wv; dst = g_wv; j = i - XF4 - 2 * WF4; }
    else                            { src = wo; dst = g_wo; j = i - XF4 - 3 * WF4; }
    float4 v = *(const float4*)(src + (size_t)j * 4);
    uint4 u = make_uint4(f2tf32(v.x), f2tf32(v.y), f2tf32(v.z), f2tf32(v.w));
    *(uint4*)(dst + (size_t)j * 4) = u;
}

// ----------------------------------------------------------------------------
// tf32 tensor-core GEMM v4:  Y[M,N] = A[M,K] @ W[N,K]^T
// Inputs pre-rounded to tf32 -> no cvt in hot loop; fragments reinterpret bits.
// cp.async double-buffered, 16B-chunk XOR swizzle, slot remap as in R13.
// RND_OUT: round epilogue to tf32 (for q/k/v), else raw fp32 (final output).
// ----------------------------------------------------------------------------
#define BM 128
#define BN 128
#define BKG 16

template <bool RND_OUT>
__device__ __forceinline__ void gemm_nt_tc(const float* __restrict__ A,
                                           const float* __restrict__ W,
                                           float* __restrict__ Y,
                                           int K, int N) {
    __shared__ float As[2][BM][16];
    __shared__ float Ws[2][BN][16];

    const int tid  = threadIdx.x;
    const int lane = tid & 31;
    const int warp = tid >> 5;
    const int wm   = warp & 1;
    const int wn   = warp >> 1;
    const int g    = lane >> 2;
    const int t4   = lane & 3;

    const int bm = blockIdx.y * BM;
    const int bn = blockIdx.x * BN;

    const int r1 = tid >> 2;            // 0..63
    const int r2 = r1 + 64;
    const int cc = tid & 3;
    const int cw = (cc ^ (r1 & 3)) * 4;

    const float* Ap1 = A + (size_t)(bm + r1) * K + cc * 4;
    const float* Ap2 = A + (size_t)(bm + r2) * K + cc * 4;
    const float* Wp1 = W + (size_t)(bn + r1) * K + cc * 4;
    const float* Wp2 = W + (size_t)(bn + r2) * K + cc * 4;

    const uint32_t sA1 = (uint32_t)__cvta_generic_to_shared(&As[0][r1][cw]);
    const uint32_t sA2 = (uint32_t)__cvta_generic_to_shared(&As[0][r2][cw]);
    const uint32_t sW1 = (uint32_t)__cvta_generic_to_shared(&Ws[0][r1][cw]);
    const uint32_t sW2 = (uint32_t)__cvta_generic_to_shared(&Ws[0][r2][cw]);
    const uint32_t stgoff = BM * 16 * 4;

    float acc[4][4][4];
#pragma unroll
    for (int i = 0; i < 4; ++i)
#pragma unroll
        for (int j = 0; j < 4; ++j)
#pragma unroll
            for (int q = 0; q < 4; ++q) acc[i][j][q] = 0.f;

    const int niter = K / BKG;

    cp_async16(sA1, Ap1);
    cp_async16(sA2, Ap2);
    cp_async16(sW1, Wp1);
    cp_async16(sW2, Wp2);
    cp_commit();

    for (int i = 0; i < niter; ++i) {
        const int s = i & 1;
        if (i + 1 < niter) {
            const uint32_t so = (uint32_t)((i + 1) & 1) * stgoff;
            const int go = (i + 1) * BKG;
            cp_async16(sA1 + so, Ap1 + go);
            cp_async16(sA2 + so, Ap2 + go);
            cp_async16(sW1 + so, Wp1 + go);
            cp_async16(sW2 + so, Wp2 + go);
            cp_commit();
            cp_wait<1>();
        } else {
            cp_wait<0>();
        }
        __syncthreads();

#pragma unroll
        for (int ksb = 0; ksb < 2; ++ksb) {
            const int chunk = ksb * 2 + (t4 >> 1);
            const int w0 = ((chunk ^ (g & 3)) << 2) + ((2 * t4) & 3);

            uint32_t af[4][4];
            uint32_t bf[4][2];
#pragma unroll
            for (int mt = 0; mt < 4; ++mt) {
                int r0 = wm * 64 + mt * 16 + g;
                uint2 p = *(const uint2*)&As[s][r0][w0];
                uint2 q = *(const uint2*)&As[s][r0 + 8][w0];
                af[mt][0] = p.x; af[mt][1] = q.x;
                af[mt][2] = p.y; af[mt][3] = q.y;
            }
#pragma unroll
            for (int nt = 0; nt < 4; ++nt) {
                int n0 = wn * 32 + nt * 8 + g;
                uint2 r = *(const uint2*)&Ws[s][n0][w0];
                bf[nt][0] = r.x; bf[nt][1] = r.y;
            }
#pragma unroll
            for (int mt = 0; mt < 4; ++mt)
#pragma unroll
                for (int nt = 0; nt < 4; ++nt)
                    mma16n8k8(acc[mt][nt], af[mt], bf[nt]);
        }
        __syncthreads();
    }

#pragma unroll
    for (int mt = 0; mt < 4; ++mt) {
        int r0 = bm + wm * 64 + mt * 16 + g;
#pragma unroll
        for (int nt = 0; nt < 4; ++nt) {
            int c = bn + wn * 32 + nt * 8 + 2 * t4;
            if (RND_OUT) {
                uint2 u0 = make_uint2(f2tf32(acc[mt][nt][0]), f2tf32(acc[mt][nt][1]));
                uint2 u1 = make_uint2(f2tf32(acc[mt][nt][2]), f2tf32(acc[mt][nt][3]));
                *(uint2*)(Y + (size_t)r0 * N + c) = u0;
                *(uint2*)(Y + (size_t)(r0 + 8) * N + c) = u1;
            } else {
                *(float2*)(Y + (size_t)r0 * N + c) =
                    make_float2(acc[mt][nt][0], acc[mt][nt][1]);
                *(float2*)(Y + (size_t)(r0 + 8) * N + c) =
                    make_float2(acc[mt][nt][2], acc[mt][nt][3]);
            }
        }
    }
}

__global__ void __launch_bounds__(256, 2)
qkv_kernel() {
    const float* W;
    float* Y;
    if (blockIdx.z == 0)      { W = g_wq; Y = g_q; }
    else if (blockIdx.z == 1) { W = g_wk; Y = g_k; }
    else                      { W = g_wv; Y = g_v; }
    gemm_nt_tc<true>(g_xr, W, Y, HID, HID);
}

__global__ void __launch_bounds__(256, 2)
proj_kernel(float* __restrict__ out) {
    gemm_nt_tc<false>(g_att, g_wo, out, HID, HID);
}

// ----------------------------------------------------------------------------
// Tensor-core causal flash attention v3: q/k/v already tf32-rounded ->
// staging is plain vector copies (Q scale by 1/8 exact on tf32).
// Epilogue rounds output to tf32 for the projection GEMM.
// ----------------------------------------------------------------------------
#define QST 72
#define KST 72
#define VST 68
#define ATTN_SMEM (128 * QST * 4)   // 36864 B

__global__ void __launch_bounds__(256, 2) attn_kernel() {
    extern __shared__ float sm[];
    float* Qs = sm;                 // [128][QST] (staging phase only)
    float* Ks = sm;                 // [64][KST]  (loop phase)
    float* Vs = sm + 64 * KST;      // [64][VST]

    const int tid  = threadIdx.x;
    const int lane = tid & 31;
    const int w    = tid >> 5;
    const int g    = lane >> 2;
    const int t4   = lane & 3;

    const int qt = (int)gridDim.x - 1 - (int)blockIdx.x;  // heavy tiles first
    const int bh = blockIdx.y;
    const int b  = bh >> 4;
    const int h  = bh & 15;
    const size_t headoff = (size_t)b * SEQ * HID + (size_t)h * HD;
    const int qbase = qt * 128;

    const int srow = tid >> 4;
    const int sch  = tid & 15;

    // ---- stage Q (x 1/8, exact on tf32 values) ----
#pragma unroll
    for (int s = 0; s < 8; ++s) {
        int r = srow + 16 * s;
        float4 v = *(const float4*)(g_q + headoff + (size_t)(qbase + r) * HID + sch * 4);
        *(float4*)&Qs[r * QST + sch * 4] =
            make_float4(v.x * 0.125f, v.y * 0.125f, v.z * 0.125f, v.w * 0.125f);
    }
    __syncthreads();

    uint32_t qf[8][4];
#pragma unroll
    for (int oct = 0; oct < 8; ++oct) {
        uint2 p0 = *(const uint2*)&Qs[(w * 16 + g) * QST + oct * 8 + 2 * t4];
        uint2 p1 = *(const uint2*)&Qs[(w * 16 + g + 8) * QST + oct * 8 + 2 * t4];
        qf[oct][0] = p0.x; qf[oct][1] = p1.x;
        qf[oct][2] = p0.y; qf[oct][3] = p1.y;
    }
    __syncthreads();

    float m0 = -1e30f, m1 = -1e30f, l0 = 0.f, l1 = 0.f;
    float oacc[8][4];
#pragma unroll
    for (int nt = 0; nt < 8; ++nt)
#pragma unroll
        for (int q = 0; q < 4; ++q) oacc[nt][q] = 0.f;

    const int row0 = qbase + w * 16 + g;
    const int row1 = row0 + 8;

    const int nkt = 2 * qt + 2;
    for (int kt = 0; kt < nkt; ++kt) {
        // ---- stage K and V (plain copies — already tf32) ----
#pragma unroll
        for (int s = 0; s < 4; ++s) {
            int r = srow + 16 * s;
            size_t goff = headoff + (size_t)(kt * 64 + r) * HID + sch * 4;
            *(uint4*)&Ks[r * KST + sch * 4] = *(const uint4*)(g_k + goff);
            *(uint4*)&Vs[r * VST + sch * 4] = *(const uint4*)(g_v + goff);
        }
        __syncthreads();

        float sacc[8][4];
#pragma unroll
        for (int nt = 0; nt < 8; ++nt)
#pragma unroll
            for (int q = 0; q < 4; ++q) sacc[nt][q] = 0.f;

#pragma unroll
        for (int nt = 0; nt < 8; ++nt) {
            const float* krow = &Ks[(nt * 8 + g) * KST + 2 * t4];
#pragma unroll
            for (int oct = 0; oct < 8; ++oct) {
                uint2 bb = *(const uint2*)(krow + oct * 8);
                uint32_t bf[2] = {bb.x, bb.y};
                mma16n8k8(sacc[nt], qf[oct], bf);
            }
        }

        if (kt >= 2 * qt) {
            int colb = kt * 64 + 2 * t4;
#pragma unroll
            for (int nt = 0; nt < 8; ++nt) {
                int c = colb + nt * 8;
                if (c     > row0) sacc[nt][0] = -1e30f;
                if (c + 1 > row0) sacc[nt][1] = -1e30f;
                if (c     > row1) sacc[nt][2] = -1e30f;
                if (c + 1 > row1) sacc[nt][3] = -1e30f;
            }
        }

        float mx0 = -1e30f, mx1 = -1e30f;
#pragma unroll
        for (int nt = 0; nt < 8; ++nt) {
            mx0 = fmaxf(mx0, fmaxf(sacc[nt][0], sacc[nt][1]));
            mx1 = fmaxf(mx1, fmaxf(sacc[nt][2], sacc[nt][3]));
        }
        mx0 = fmaxf(mx0, __shfl_xor_sync(0xffffffffu, mx0, 1));
        mx0 = fmaxf(mx0, __shfl_xor_sync(0xffffffffu, mx0, 2));
        mx1 = fmaxf(mx1, __shfl_xor_sync(0xffffffffu, mx1, 1));
        mx1 = fmaxf(mx1, __shfl_xor_sync(0xffffffffu, mx1, 2));

        float mn0 = fmaxf(m0, mx0), mn1 = fmaxf(m1, mx1);
        float al0 = __expf(m0 - mn0), al1 = __expf(m1 - mn1);
        m0 = mn0; m1 = mn1;

        float rs0 = 0.f, rs1 = 0.f;
#pragma unroll
        for (int nt = 0; nt < 8; ++nt) {
            sacc[nt][0] = __expf(sacc[nt][0] - m0);
            sacc[nt][1] = __expf(sacc[nt][1] - m0);
            sacc[nt][2] = __expf(sacc[nt][2] - m1);
            sacc[nt][3] = __expf(sacc[nt][3] - m1);
            rs0 += sacc[nt][0] + sacc[nt][1];
            rs1 += sacc[nt][2] + sacc[nt][3];
            oacc[nt][0] *= al0; oacc[nt][1] *= al0;
            oacc[nt][2] *= al1; oacc[nt][3] *= al1;
        }
        rs0 += __shfl_xor_sync(0xffffffffu, rs0, 1);
        rs0 += __shfl_xor_sync(0xffffffffu, rs0, 2);
        rs1 += __shfl_xor_sync(0xffffffffu, rs1, 1);
        rs1 += __shfl_xor_sync(0xffffffffu, rs1, 2);
        l0 = l0 * al0 + rs0;
        l1 = l1 * al1 + rs1;

#pragma unroll
        for (int oct = 0; oct < 8; ++oct) {
            uint32_t af[4] = {f2tf32(sacc[oct][0]), f2tf32(sacc[oct][2]),
                              f2tf32(sacc[oct][1]), f2tf32(sacc[oct][3])};
            const float* vrow0 = &Vs[(oct * 8 + 2 * t4) * VST + g];
#pragma unroll
            for (int nt = 0; nt < 8; ++nt) {
                uint32_t bf[2] = {__float_as_uint(vrow0[nt * 8]),
                                  __float_as_uint(vrow0[VST + nt * 8])};
                mma16n8k8(oacc[nt], af, bf);
            }
        }
        __syncthreads();
    }

    // epilogue: write tf32-rounded att (consumed by proj GEMM)
    float inv0 = 1.f / l0, inv1 = 1.f / l1;
    float* o0 = g_att + headoff + (size_t)(qbase + w * 16 + g) * HID;
    float* o1 = o0 + (size_t)8 * HID;
#pragma unroll
    for (int nt = 0; nt < 8; ++nt) {
        int c = nt * 8 + 2 * t4;
        *(uint2*)(o0 + c) = make_uint2(f2tf32(oacc[nt][0] * inv0),
                                       f2tf32(oacc[nt][1] * inv0));
        *(uint2*)(o1 + c) = make_uint2(f2tf32(oacc[nt][2] * inv1),
                                       f2tf32(oacc[nt][3] * inv1));
    }
}

// ----------------------------------------------------------------------------
extern "C" void kernel_launch(void* const* d_in, const int* in_sizes, int n_in,
                              void* d_out, int out_size) {
    const float* x  = (const float*)d_in[0];
    const float* Wq = (const float*)d_in[1];
    const float* Wk = (const float*)d_in[2];
    const float* Wv = (const float*)d_in[3];
    const float* Wo = (const float*)d_in[4];
    float* out = (float*)d_out;

    cudaFuncSetAttribute(attn_kernel,
                         cudaFuncAttributeMaxDynamicSharedMemorySize, ATTN_SMEM);

    round_kernel<<<(XF4 + 4 * WF4) / 256, 256>>>(x, Wq, Wk, Wv, Wo);

    dim3 gqkv(HID / BN, MROWS / BM, 3);     // 8 x 32 x 3
    qkv_kernel<<<gqkv, 256>>>();

    dim3 gattn(SEQ / 128, NB * NHEAD);      // 16 x 32
    attn_kernel<<<gattn, 256, ATTN_SMEM>>>();

    dim3 gproj(HID / BN, MROWS / BM);       // 8 x 32
    proj_kernel<<<gproj, 256>>>(out);
}